// round 9
// baseline (speedup 1.0000x reference)
#include <cuda_runtime.h>

#define BB 8
#define DD 4096
#define HH 32
#define HDD 128
#define KVV 512
#define PASTN 8191
#define TOTALN 8192
#define SCALEF 0.08838834764831845f  // 128^-0.5
#define NSC 32   // s-splits for k_ov / k_scores (256 s per block)
#define NKC 16   // k-splits for qabs

// ---------------- scratch ----------------
__device__ float g_cnew[BB * KVV];
__device__ float g_qabs[BB * HH * KVV];        // zero-init, atomic accumulate
__device__ float g_scores[BB * HH * TOTALN];
__device__ float g_ml2[BB * HH * 2];           // (rowmax, 1/rowsum)
__device__ float g_opart[NSC * BB * HH * KVV];
__device__ float g_oc[BB * HH * KVV];
__device__ float g_ohead[BB * HH * HDD];

// packed dual-fp32 FMA (sm_100+)
__device__ __forceinline__ float2 ffma2(const float2 a, const float2 b, const float2 c) {
    float2 d;
    asm("fma.rn.f32x2 %0, %1, %2, %3;"
        : "=l"(*(unsigned long long*)&d)
        : "l"(*(const unsigned long long*)&a),
          "l"(*(const unsigned long long*)&b),
          "l"(*(const unsigned long long*)&c));
    return d;
}
// scalar-broadcast form: dup built in regs (ALU), not smem
__device__ __forceinline__ float2 ffma2s(const float a, const float2 b, const float2 c) {
    return ffma2(make_float2(a, a), b, c);
}

__device__ __forceinline__ void cp_async16(unsigned s, const void* g) {
    asm volatile("cp.async.cg.shared.global [%0], [%1], 16;" :: "r"(s), "l"(g));
}
__device__ __forceinline__ void cp_commit() {
    asm volatile("cp.async.commit_group;");
}

// ---------------- K0: zero d_out, g_cnew, g_ohead, g_qabs ----------------
__global__ void k_init(float* __restrict__ out) {
    int i = blockIdx.x * 256 + threadIdx.x;       // 131072 threads
    g_qabs[i] = 0.f;
    if (i < BB * DD) { out[i] = 0.f; g_ohead[i] = 0.f; }
    if (i < BB * KVV) g_cnew[i] = 0.f;
}

// ---------------- K1: c_new = x @ w_compress (k-split, atomic) ----------------
__global__ __launch_bounds__(256) void k_compress(const float* __restrict__ x,
                                                  const float* __restrict__ wc) {
    __shared__ float xs[128][9];   // [k][b] scalar
    int kc = blockIdx.x;           // 32 chunks of 128 k
    int tid = threadIdx.x;
    for (int i = tid; i < 1024; i += 256) {
        int k = i >> 3, b = i & 7;
        xs[k][b] = x[b * DD + kc * 128 + k];
    }
    __syncthreads();
    float2 acc[BB];
    #pragma unroll
    for (int b = 0; b < BB; b++) acc[b] = make_float2(0.f, 0.f);
    const float* wp = wc + (size_t)kc * 128 * KVV + tid * 2;
    #pragma unroll 8
    for (int k = 0; k < 128; k++) {
        float2 w2 = *(const float2*)(wp + (size_t)k * KVV);
        float4 x0 = *(const float4*)&xs[k][0];
        float4 x1 = *(const float4*)&xs[k][4];
        acc[0] = ffma2s(x0.x, w2, acc[0]);
        acc[1] = ffma2s(x0.y, w2, acc[1]);
        acc[2] = ffma2s(x0.z, w2, acc[2]);
        acc[3] = ffma2s(x0.w, w2, acc[3]);
        acc[4] = ffma2s(x1.x, w2, acc[4]);
        acc[5] = ffma2s(x1.y, w2, acc[5]);
        acc[6] = ffma2s(x1.z, w2, acc[6]);
        acc[7] = ffma2s(x1.w, w2, acc[7]);
    }
    #pragma unroll
    for (int b = 0; b < BB; b++) {
        atomicAdd(&g_cnew[b * KVV + tid * 2 + 0], acc[b].x);
        atomicAdd(&g_cnew[b * KVV + tid * 2 + 1], acc[b].y);
    }
}

// ---------------- K2: q_abs (scale folded into x), atomic accumulate ----------------
// grid (kc=16, h=32); 128 threads; thread owns n-quad tid*4
__global__ __launch_bounds__(128) void k_qabs(const float* __restrict__ x,
                                              const float* __restrict__ aqk) {
    __shared__ float xs[256][9];   // [k][b] scalar, pre-scaled
    int kc = blockIdx.x;
    int h  = blockIdx.y;
    int tid = threadIdx.x;
    for (int i = tid; i < 2048; i += 128) {
        int k = i >> 3, b = i & 7;
        xs[k][b] = x[b * DD + kc * 256 + k] * SCALEF;
    }
    __syncthreads();
    float2 acc[BB][2];
    #pragma unroll
    for (int b = 0; b < BB; b++) {
        acc[b][0] = make_float2(0.f, 0.f);
        acc[b][1] = make_float2(0.f, 0.f);
    }
    const float* ap = aqk + ((size_t)h * DD + (size_t)kc * 256) * KVV + tid * 4;
    #pragma unroll 8
    for (int k = 0; k < 256; k++) {
        float4 a4 = *(const float4*)(ap + (size_t)k * KVV);
        float2 alo = make_float2(a4.x, a4.y);
        float2 ahi = make_float2(a4.z, a4.w);
        float4 x0 = *(const float4*)&xs[k][0];
        float4 x1 = *(const float4*)&xs[k][4];
        acc[0][0] = ffma2s(x0.x, alo, acc[0][0]); acc[0][1] = ffma2s(x0.x, ahi, acc[0][1]);
        acc[1][0] = ffma2s(x0.y, alo, acc[1][0]); acc[1][1] = ffma2s(x0.y, ahi, acc[1][1]);
        acc[2][0] = ffma2s(x0.z, alo, acc[2][0]); acc[2][1] = ffma2s(x0.z, ahi, acc[2][1]);
        acc[3][0] = ffma2s(x0.w, alo, acc[3][0]); acc[3][1] = ffma2s(x0.w, ahi, acc[3][1]);
        acc[4][0] = ffma2s(x1.x, alo, acc[4][0]); acc[4][1] = ffma2s(x1.x, ahi, acc[4][1]);
        acc[5][0] = ffma2s(x1.y, alo, acc[5][0]); acc[5][1] = ffma2s(x1.y, ahi, acc[5][1]);
        acc[6][0] = ffma2s(x1.z, alo, acc[6][0]); acc[6][1] = ffma2s(x1.z, ahi, acc[6][1]);
        acc[7][0] = ffma2s(x1.w, alo, acc[7][0]); acc[7][1] = ffma2s(x1.w, ahi, acc[7][1]);
    }
    #pragma unroll
    for (int b = 0; b < BB; b++) {
        float* dst = &g_qabs[((size_t)b * HH + h) * KVV + tid * 4];
        atomicAdd(dst + 0, acc[b][0].x);
        atomicAdd(dst + 1, acc[b][0].y);
        atomicAdd(dst + 2, acc[b][1].x);
        atomicAdd(dst + 3, acc[b][1].y);
    }
}

// ---------------- K3: scores — 256 thr, 2 blocks/SM, scalar-q smem ----------------
// grid (sc=32, b=8); 8 warps = 4 hgrp x 2 kgrp; block = 256 s x 512 k, 16 chunks of 32 k.
// smem (floats): cs[2][32k][256s] @0/@8192; stage[256][36] @16384; q[2][32k][36] @25600/@26752.
#define CS0 0
#define CS1 8192
#define STGO 16384
#define QD0 25600
#define QD1 26752
#define SMEM_SC (27904 * 4)   // 111616 B

__global__ __launch_bounds__(256, 2) void k_scores(const float* __restrict__ past_c) {
    extern __shared__ float sm[];
    int sc = blockIdx.x, b = blockIdx.y;
    int tid = threadIdx.x;
    int S0 = sc * 256;
    unsigned sb;
    asm("{.reg .u64 t; cvta.to.shared.u64 t, %1; cvt.u32.u64 %0, t;}" : "=r"(sb) : "l"(sm));
    int w = tid >> 5, lane = tid & 31;
    int hgrp = w >> 1, kgrp = w & 1;

    // prologue: issue chunk 0 into stage (thread = one s row, 128 B contiguous)
    {
        int s = tid;
        const float* row = (S0 + s < PASTN) ? past_c + ((size_t)b * PASTN + S0 + s) * KVV
                                            : g_cnew + b * KVV;
        #pragma unroll
        for (int kq = 0; kq < 8; kq++)
            cp_async16(sb + (unsigned)(STGO + s * 36 + kq * 4) * 4u, row + kq * 4);
    }
    cp_commit();

    float2 acc[8][4];
    #pragma unroll
    for (int i = 0; i < 8; i++)
        #pragma unroll
        for (int j = 0; j < 4; j++) acc[i][j] = make_float2(0.f, 0.f);

    for (int hk = 0; hk < 16; hk++) {
        int kb = hk * 32;
        asm volatile("cp.async.wait_group 0;");
        __syncthreads();                       // stage ready; prev compute done
        // transpose stage[s][36] -> cs[hk&1][k][256]
        {
            const float* st = sm + STGO + tid * 36;
            float* cs = sm + ((hk & 1) ? CS1 : CS0);
            #pragma unroll
            for (int q = 0; q < 8; q++) {
                float4 v = *(const float4*)(st + q * 4);
                cs[(q * 4 + 0) * 256 + tid] = v.x;
                cs[(q * 4 + 1) * 256 + tid] = v.y;
                cs[(q * 4 + 2) * 256 + tid] = v.z;
                cs[(q * 4 + 3) * 256 + tid] = v.w;
            }
        }
        // q fill (scalar): warp w handles h = w, w+8, w+16, w+24; lane = k
        {
            float* qd = sm + ((hk & 1) ? QD1 : QD0);
            #pragma unroll
            for (int t = 0; t < 4; t++) {
                int h = w + t * 8;
                qd[lane * 36 + h] = g_qabs[((size_t)b * HH + h) * KVV + kb + lane];
            }
        }
        __syncthreads();                       // stage reads done; cs/qd visible
        if (hk < 15) {                         // stage free -> issue next chunk
            int kb2 = kb + 32;
            int s = tid;
            const float* row = (S0 + s < PASTN) ? past_c + ((size_t)b * PASTN + S0 + s) * KVV
                                                : g_cnew + b * KVV;
            #pragma unroll
            for (int kq = 0; kq < 8; kq++)
                cp_async16(sb + (unsigned)(STGO + s * 36 + kq * 4) * 4u, row + kb2 + kq * 4);
            cp_commit();
        }
        // compute (16 k per warp via kgrp)
        {
            const float* cs = sm + ((hk & 1) ? CS1 : CS0);
            const float* qd = sm + ((hk & 1) ? QD1 : QD0);
            #pragma unroll 2
            for (int k = kgrp * 16; k < kgrp * 16 + 16; k++) {
                float4 qa = *(const float4*)(qd + k * 36 + hgrp * 8);
                float4 qb = *(const float4*)(qd + k * 36 + hgrp * 8 + 4);
                float2 c2[4];
                #pragma unroll
                for (int j = 0; j < 4; j++)
                    c2[j] = *(const float2*)&cs[k * 256 + lane * 2 + j * 64];
                #pragma unroll
                for (int j = 0; j < 4; j++) {
                    acc[0][j] = ffma2s(qa.x, c2[j], acc[0][j]);
                    acc[1][j] = ffma2s(qa.y, c2[j], acc[1][j]);
                    acc[2][j] = ffma2s(qa.z, c2[j], acc[2][j]);
                    acc[3][j] = ffma2s(qa.w, c2[j], acc[3][j]);
                    acc[4][j] = ffma2s(qb.x, c2[j], acc[4][j]);
                    acc[5][j] = ffma2s(qb.y, c2[j], acc[5][j]);
                    acc[6][j] = ffma2s(qb.z, c2[j], acc[6][j]);
                    acc[7][j] = ffma2s(qb.w, c2[j], acc[7][j]);
                }
            }
        }
    }
    // cross-kgrp reduction through smem (reuse cs0), then store
    __syncthreads();
    float2* red = (float2*)sm;
    if (kgrp == 1) {
        #pragma unroll
        for (int i = 0; i < 8; i++)
            #pragma unroll
            for (int j = 0; j < 4; j++)
                red[((hgrp * 32 + lane) * 8 + i) * 4 + j] = acc[i][j];
    }
    __syncthreads();
    if (kgrp == 0) {
        #pragma unroll
        for (int i = 0; i < 8; i++)
            #pragma unroll
            for (int j = 0; j < 4; j++) {
                float2 p = red[((hgrp * 32 + lane) * 8 + i) * 4 + j];
                acc[i][j].x += p.x; acc[i][j].y += p.y;
                *(float2*)&g_scores[((size_t)b * HH + hgrp * 8 + i) * TOTALN
                                    + S0 + lane * 2 + j * 64] = acc[i][j];
            }
    }
}

// ---------------- K4: row stats (m, 1/l) per (b,h) ----------------
__global__ __launch_bounds__(256) void k_mrow() {
    int bh = blockIdx.x;
    int tid = threadIdx.x;
    int w = tid >> 5, lane = tid & 31;
    const float* row = g_scores + (size_t)bh * TOTALN;
    float4 v[8];
    #pragma unroll
    for (int i = 0; i < 8; i++) v[i] = ((const float4*)row)[tid * 8 + i];
    float m = -1e30f;
    #pragma unroll
    for (int i = 0; i < 8; i++)
        m = fmaxf(m, fmaxf(fmaxf(v[i].x, v[i].y), fmaxf(v[i].z, v[i].w)));
    #pragma unroll
    for (int o = 16; o; o >>= 1) m = fmaxf(m, __shfl_xor_sync(0xffffffffu, m, o));
    __shared__ float redm[8], reds[8];
    if (lane == 0) redm[w] = m;
    __syncthreads();
    m = redm[0];
    #pragma unroll
    for (int i = 1; i < 8; i++) m = fmaxf(m, redm[i]);
    float s = 0.f;
    #pragma unroll
    for (int i = 0; i < 8; i++)
        s += __expf(v[i].x - m) + __expf(v[i].y - m) + __expf(v[i].z - m) + __expf(v[i].w - m);
    #pragma unroll
    for (int o = 16; o; o >>= 1) s += __shfl_xor_sync(0xffffffffu, s, o);
    if (lane == 0) reds[w] = s;
    __syncthreads();
    if (tid == 0) {
        s = reds[0] + reds[1] + reds[2] + reds[3] + reds[4] + reds[5] + reds[6] + reds[7];
        g_ml2[bh * 2 + 0] = m;
        g_ml2[bh * 2 + 1] = 1.f / s;
    }
}

// ---------------- K5: o_c partials — 256 thr, 2 blocks/SM, scalar-attn smem ----------------
// grid (sc=32, b=8); 8 warps = 4 hgrp x 2 ngrp; block = 256 s x 512 n, 16 chunks of 16 s.
// smem: cb[2][16s][512n] @0/@8192 (65536 B); ad[16s][36] @16384 (2304 B).
#define ADOFF 16384
#define SMEM_OV (16960 * 4)   // 67840 B

__global__ __launch_bounds__(256, 2) void k_ov(const float* __restrict__ past_c) {
    extern __shared__ float sm[];
    __shared__ float msh[HH], ilsh[HH];
    int sc = blockIdx.x, b = blockIdx.y;
    int tid = threadIdx.x;
    unsigned sb;
    asm("{.reg .u64 t; cvta.to.shared.u64 t, %1; cvt.u32.u64 %0, t;}" : "=r"(sb) : "l"(sm));
    int S0 = sc * 256;
    int w = tid >> 5, lane = tid & 31;
    int hgrp = w >> 1, ngrp = w & 1;
    if (tid < HH) {
        msh[tid]  = g_ml2[(b * HH + tid) * 2 + 0];
        ilsh[tid] = g_ml2[(b * HH + tid) * 2 + 1];
    }
    float2 acc[8][4];
    #pragma unroll
    for (int i = 0; i < 8; i++)
        #pragma unroll
        for (int j = 0; j < 4; j++) acc[i][j] = make_float2(0.f, 0.f);

    // prologue: issue chunk 0 (16 s x 512 n)
    #pragma unroll
    for (int t = 0; t < 8; t++) {
        int i = tid + t * 256;
        int s = i >> 7, n4 = i & 127;
        const float* row = (S0 + s < PASTN) ? past_c + ((size_t)b * PASTN + S0 + s) * KVV
                                            : g_cnew + b * KVV;
        cp_async16(sb + (unsigned)(s * 512 + n4 * 4) * 4u, row + n4 * 4);
    }
    cp_commit();

    float* ad = sm + ADOFF;
    for (int ch = 0; ch < 16; ch++) {
        int s0 = S0 + ch * 16;
        asm volatile("cp.async.wait_group 0;");
        __syncthreads();                   // chunk visible; prev compute done
        // ad fill (scalar): i -> (s = i&15, h = i>>4)
        #pragma unroll
        for (int t = 0; t < 2; t++) {
            int i = tid + t * 256;
            int s = i & 15, h = i >> 4;
            float e = __expf(g_scores[((size_t)b * HH + h) * TOTALN + s0 + s] - msh[h]) * ilsh[h];
            ad[s * 36 + h] = e;
        }
        if (ch < 15) {                     // issue next into other buffer
            int s0n = s0 + 16;
            int base = ((ch + 1) & 1) * 8192;
            #pragma unroll
            for (int t = 0; t < 8; t++) {
                int i = tid + t * 256;
                int s = i >> 7, n4 = i & 127;
                const float* row = (s0n + s < PASTN) ? past_c + ((size_t)b * PASTN + s0n + s) * KVV
                                                     : g_cnew + b * KVV;
                cp_async16(sb + (unsigned)(base + s * 512 + n4 * 4) * 4u, row + n4 * 4);
            }
            cp_commit();
        }
        __syncthreads();                   // ad visible
        const float* c_s = sm + (ch & 1) * 8192;
        #pragma unroll 2
        for (int s = 0; s < 16; s++) {
            float4 aa = *(const float4*)(ad + s * 36 + hgrp * 8);
            float4 ab = *(const float4*)(ad + s * 36 + hgrp * 8 + 4);
            float2 c2[4];
            #pragma unroll
            for (int j = 0; j < 4; j++)
                c2[j] = *(const float2*)&c_s[s * 512 + ngrp * 256 + j * 64 + lane * 2];
            #pragma unroll
            for (int j = 0; j < 4; j++) {
                acc[0][j] = ffma2s(aa.x, c2[j], acc[0][j]);
                acc[1][j] = ffma2s(aa.y, c2[j], acc[1][j]);
                acc[2][j] = ffma2s(aa.z, c2[j], acc[2][j]);
                acc[3][j] = ffma2s(aa.w, c2[j], acc[3][j]);
                acc[4][j] = ffma2s(ab.x, c2[j], acc[4][j]);
                acc[5][j] = ffma2s(ab.y, c2[j], acc[5][j]);
                acc[6][j] = ffma2s(ab.z, c2[j], acc[6][j]);
                acc[7][j] = ffma2s(ab.w, c2[j], acc[7][j]);
            }
        }
    }
    // each warp owns distinct (h,n) tile — store directly, no reduction
    #pragma unroll
    for (int i = 0; i < 8; i++)
        #pragma unroll
        for (int j = 0; j < 4; j++)
            *(float2*)&g_opart[(((size_t)sc * BB + b) * HH + hgrp * 8 + i) * KVV
                               + ngrp * 256 + j * 64 + lane * 2] = acc[i][j];
}

// reduce NSC s-partials -> g_oc
__global__ void k_redo() {
    int i = blockIdx.x * 256 + threadIdx.x;
    const float4* p = (const float4*)g_opart;
    float4 s = make_float4(0.f, 0.f, 0.f, 0.f);
    #pragma unroll
    for (int c = 0; c < NSC; c++) {
        float4 t = p[c * 32768 + i];
        s.x += t.x; s.y += t.y; s.z += t.z; s.w += t.w;
    }
    ((float4*)g_oc)[i] = s;
}

// ---------------- K6: per-head v-up (n-split, atomic) ----------------
__global__ __launch_bounds__(128) void k_vup(const float* __restrict__ wv) {
    __shared__ float od[128][9];   // [n_local][b] scalar
    int h = blockIdx.x, nc = blockIdx.y;
    int tid = threadIdx.x;
    int jp = tid & 63, g = tid >> 6;
    for (int i = tid; i < 1024; i += 128) {
        int n = i >> 3, b = i & 7;
        od[n][b] = g_oc[((size_t)b * HH + h) * KVV + nc * 128 + n];
    }
    __syncthreads();
    float2 acc[BB];
    #pragma unroll
    for (int b = 0; b < BB; b++) acc[b] = make_float2(0.f, 0.f);
    const float* wp = wv + (size_t)(nc * 128 + g * 64) * (HH * HDD) + h * HDD + jp * 2;
    #pragma unroll 8
    for (int n = 0; n < 64; n++) {
        float2 w2 = *(const float2*)(wp + (size_t)n * (HH * HDD));
        float4 o0 = *(const float4*)&od[g * 64 + n][0];
        float4 o1 = *(const float4*)&od[g * 64 + n][4];
        acc[0] = ffma2s(o0.x, w2, acc[0]);
        acc[1] = ffma2s(o0.y, w2, acc[1]);
        acc[2] = ffma2s(o0.z, w2, acc[2]);
        acc[3] = ffma2s(o0.w, w2, acc[3]);
        acc[4] = ffma2s(o1.x, w2, acc[4]);
        acc[5] = ffma2s(o1.y, w2, acc[5]);
        acc[6] = ffma2s(o1.z, w2, acc[6]);
        acc[7] = ffma2s(o1.w, w2, acc[7]);
    }
    #pragma unroll
    for (int b = 0; b < BB; b++) {
        atomicAdd(&g_ohead[b * DD + h * HDD + jp * 2 + 0], acc[b].x);
        atomicAdd(&g_ohead[b * DD + h * HDD + jp * 2 + 1], acc[b].y);
    }
}

// ---------------- K7: out = out_head @ w_o (m-split over 16, atomic) ----------------
__global__ __launch_bounds__(128) void k_oproj(const float* __restrict__ wo,
                                               float* __restrict__ out) {
    __shared__ float ohd[256][9];   // [m_local][b] scalar
    int dt = blockIdx.x, mc = blockIdx.y;
    int tid = threadIdx.x;
    for (int i = tid; i < 2048; i += 128) {
        int m = i >> 3, b = i & 7;
        ohd[m][b] = g_ohead[b * DD + mc * 256 + m];
    }
    __syncthreads();
    float2 acc[BB];
    #pragma unroll
    for (int b = 0; b < BB; b++) acc[b] = make_float2(0.f, 0.f);
    const float* wp = wo + (size_t)mc * 256 * DD + dt * 256 + tid * 2;
    #pragma unroll 8
    for (int m = 0; m < 256; m++) {
        float2 w2 = *(const float2*)(wp + (size_t)m * DD);
        float4 o0 = *(const float4*)&ohd[m][0];
        float4 o1 = *(const float4*)&ohd[m][4];
        acc[0] = ffma2s(o0.x, w2, acc[0]);
        acc[1] = ffma2s(o0.y, w2, acc[1]);
        acc[2] = ffma2s(o0.z, w2, acc[2]);
        acc[3] = ffma2s(o0.w, w2, acc[3]);
        acc[4] = ffma2s(o1.x, w2, acc[4]);
        acc[5] = ffma2s(o1.y, w2, acc[5]);
        acc[6] = ffma2s(o1.z, w2, acc[6]);
        acc[7] = ffma2s(o1.w, w2, acc[7]);
    }
    #pragma unroll
    for (int b = 0; b < BB; b++) {
        atomicAdd(&out[b * DD + dt * 256 + tid * 2 + 0], acc[b].x);
        atomicAdd(&out[b * DD + dt * 256 + tid * 2 + 1], acc[b].y);
    }
}

// ---------------- launch ----------------
extern "C" void kernel_launch(void* const* d_in, const int* in_sizes, int n_in,
                              void* d_out, int out_size) {
    const float* x      = (const float*)d_in[0];
    const float* past_c = (const float*)d_in[1];
    const float* aqk    = (const float*)d_in[2];
    const float* wc     = (const float*)d_in[3];
    const float* wv     = (const float*)d_in[4];
    const float* wo     = (const float*)d_in[5];
    float* out = (float*)d_out;

    cudaFuncSetAttribute(k_scores, cudaFuncAttributeMaxDynamicSharedMemorySize, SMEM_SC);
    cudaFuncSetAttribute(k_ov,     cudaFuncAttributeMaxDynamicSharedMemorySize, SMEM_OV);

    k_init<<<512, 256>>>(out);                          // idx 0
    k_compress<<<32, 256>>>(x, wc);                     // idx 1
    k_qabs<<<dim3(NKC, 32), 128>>>(x, aqk);             // idx 2
    k_scores<<<dim3(32, 8), 256, SMEM_SC>>>(past_c);    // idx 3  <- profiled
    k_mrow<<<256, 256>>>();                             // idx 4
    k_ov<<<dim3(32, 8), 256, SMEM_OV>>>(past_c);        // idx 5
    k_redo<<<128, 256>>>();                             // idx 6
    k_vup<<<dim3(32, 4), 128>>>(wv);                    // idx 7
    k_oproj<<<dim3(16, 16), 128>>>(wo, out);            // idx 8
}

// round 11
// speedup vs baseline: 1.0819x; 1.0819x over previous
#include <cuda_runtime.h>

#define BB 8
#define DD 4096
#define HH 32
#define HDD 128
#define KVV 512
#define PASTN 8191
#define TOTALN 8192
#define SCALEF 0.08838834764831845f  // 128^-0.5
#define NSC 16   // s-splits for k_ov
#define NKC 16   // k-splits for qabs

// ---------------- scratch ----------------
__device__ float g_cnew[BB * KVV];
__device__ float g_qabs[BB * HH * KVV];        // zero-init, atomic accumulate
__device__ float g_scores[BB * HH * TOTALN];
__device__ float g_ml2[BB * HH * 2];           // (rowmax, 1/rowsum)
__device__ float g_opart[NSC * BB * HH * KVV];
__device__ float g_oc[BB * HH * KVV];
__device__ float g_ohead[BB * HH * HDD];

// packed dual-fp32 FMA (sm_100+)
__device__ __forceinline__ float2 ffma2(const float2 a, const float2 b, const float2 c) {
    float2 d;
    asm("fma.rn.f32x2 %0, %1, %2, %3;"
        : "=l"(*(unsigned long long*)&d)
        : "l"(*(const unsigned long long*)&a),
          "l"(*(const unsigned long long*)&b),
          "l"(*(const unsigned long long*)&c));
    return d;
}
// scalar-broadcast form: dup built in regs (ALU), not smem
__device__ __forceinline__ float2 ffma2s(const float a, const float2 b, const float2 c) {
    return ffma2(make_float2(a, a), b, c);
}

__device__ __forceinline__ void cp_async16(unsigned s, const void* g) {
    asm volatile("cp.async.cg.shared.global [%0], [%1], 16;" :: "r"(s), "l"(g));
}
__device__ __forceinline__ void cp_commit() {
    asm volatile("cp.async.commit_group;");
}

// ---------------- K0: zero d_out, g_cnew, g_ohead, g_qabs ----------------
__global__ void k_init(float* __restrict__ out) {
    int i = blockIdx.x * 256 + threadIdx.x;       // 131072 threads
    g_qabs[i] = 0.f;
    if (i < BB * DD) { out[i] = 0.f; g_ohead[i] = 0.f; }
    if (i < BB * KVV) g_cnew[i] = 0.f;
}

// ---------------- K1: c_new = x @ w_compress (k-split, atomic) ----------------
__global__ __launch_bounds__(256) void k_compress(const float* __restrict__ x,
                                                  const float* __restrict__ wc) {
    __shared__ float xs[128][9];   // [k][b] scalar
    int kc = blockIdx.x;           // 32 chunks of 128 k
    int tid = threadIdx.x;
    for (int i = tid; i < 1024; i += 256) {
        int k = i >> 3, b = i & 7;
        xs[k][b] = x[b * DD + kc * 128 + k];
    }
    __syncthreads();
    float2 acc[BB];
    #pragma unroll
    for (int b = 0; b < BB; b++) acc[b] = make_float2(0.f, 0.f);
    const float* wp = wc + (size_t)kc * 128 * KVV + tid * 2;
    #pragma unroll 8
    for (int k = 0; k < 128; k++) {
        float2 w2 = *(const float2*)(wp + (size_t)k * KVV);
        float4 x0 = *(const float4*)&xs[k][0];
        float4 x1 = *(const float4*)&xs[k][4];
        acc[0] = ffma2s(x0.x, w2, acc[0]);
        acc[1] = ffma2s(x0.y, w2, acc[1]);
        acc[2] = ffma2s(x0.z, w2, acc[2]);
        acc[3] = ffma2s(x0.w, w2, acc[3]);
        acc[4] = ffma2s(x1.x, w2, acc[4]);
        acc[5] = ffma2s(x1.y, w2, acc[5]);
        acc[6] = ffma2s(x1.z, w2, acc[6]);
        acc[7] = ffma2s(x1.w, w2, acc[7]);
    }
    #pragma unroll
    for (int b = 0; b < BB; b++) {
        atomicAdd(&g_cnew[b * KVV + tid * 2 + 0], acc[b].x);
        atomicAdd(&g_cnew[b * KVV + tid * 2 + 1], acc[b].y);
    }
}

// ---------------- K2: q_abs (scale folded into x), atomic accumulate ----------------
// grid (kc=16, h=32); 128 threads; thread owns n-quad tid*4
__global__ __launch_bounds__(128) void k_qabs(const float* __restrict__ x,
                                              const float* __restrict__ aqk) {
    __shared__ float xs[256][9];   // [k][b] scalar, pre-scaled
    int kc = blockIdx.x;
    int h  = blockIdx.y;
    int tid = threadIdx.x;
    for (int i = tid; i < 2048; i += 128) {
        int k = i >> 3, b = i & 7;
        xs[k][b] = x[b * DD + kc * 256 + k] * SCALEF;
    }
    __syncthreads();
    float2 acc[BB][2];
    #pragma unroll
    for (int b = 0; b < BB; b++) {
        acc[b][0] = make_float2(0.f, 0.f);
        acc[b][1] = make_float2(0.f, 0.f);
    }
    const float* ap = aqk + ((size_t)h * DD + (size_t)kc * 256) * KVV + tid * 4;
    #pragma unroll 8
    for (int k = 0; k < 256; k++) {
        float4 a4 = *(const float4*)(ap + (size_t)k * KVV);
        float2 alo = make_float2(a4.x, a4.y);
        float2 ahi = make_float2(a4.z, a4.w);
        float4 x0 = *(const float4*)&xs[k][0];
        float4 x1 = *(const float4*)&xs[k][4];
        acc[0][0] = ffma2s(x0.x, alo, acc[0][0]); acc[0][1] = ffma2s(x0.x, ahi, acc[0][1]);
        acc[1][0] = ffma2s(x0.y, alo, acc[1][0]); acc[1][1] = ffma2s(x0.y, ahi, acc[1][1]);
        acc[2][0] = ffma2s(x0.z, alo, acc[2][0]); acc[2][1] = ffma2s(x0.z, ahi, acc[2][1]);
        acc[3][0] = ffma2s(x0.w, alo, acc[3][0]); acc[3][1] = ffma2s(x0.w, ahi, acc[3][1]);
        acc[4][0] = ffma2s(x1.x, alo, acc[4][0]); acc[4][1] = ffma2s(x1.x, ahi, acc[4][1]);
        acc[5][0] = ffma2s(x1.y, alo, acc[5][0]); acc[5][1] = ffma2s(x1.y, ahi, acc[5][1]);
        acc[6][0] = ffma2s(x1.z, alo, acc[6][0]); acc[6][1] = ffma2s(x1.z, ahi, acc[6][1]);
        acc[7][0] = ffma2s(x1.w, alo, acc[7][0]); acc[7][1] = ffma2s(x1.w, ahi, acc[7][1]);
    }
    #pragma unroll
    for (int b = 0; b < BB; b++) {
        float* dst = &g_qabs[((size_t)b * HH + h) * KVV + tid * 4];
        atomicAdd(dst + 0, acc[b][0].x);
        atomicAdd(dst + 1, acc[b][0].y);
        atomicAdd(dst + 2, acc[b][1].x);
        atomicAdd(dst + 3, acc[b][1].y);
    }
}

// ---------------- K3: scores — R7 shape (512 thr, 16x8 grid) + scalar-q smem ----------------
// warp = (hgrp[4] x sgrp[2] x kgrp[2]).
// smem (floats): cs[2][32k][512s] @0/@16384; stage[512][36] @32768;
//                q scalar [2][32k][36] @51200/@52352. total 53504 fl = 214016 B.
#define CS0 0
#define CS1 16384
#define STGO 32768
#define QD0 51200
#define QD1 52352
#define SMEM_SC (53504 * 4)

__global__ __launch_bounds__(512) void k_scores(const float* __restrict__ past_c) {
    extern __shared__ float sm[];
    int sc = blockIdx.x, b = blockIdx.y;
    int tid = threadIdx.x;
    int S0 = sc * 512;
    unsigned sb;
    asm("{.reg .u64 t; cvta.to.shared.u64 t, %1; cvt.u32.u64 %0, t;}" : "=r"(sb) : "l"(sm));
    int w = tid >> 5, lane = tid & 31;
    int hgrp = w >> 2, sgrp = (w >> 1) & 1, kgrp = w & 1;

    // prologue: issue chunk 0 into stage
    #pragma unroll
    for (int j = 0; j < 8; j++) {
        int i = tid + j * 512;
        int s = i >> 3, kq = i & 7;
        const float* row = (S0 + s < PASTN) ? past_c + ((size_t)b * PASTN + S0 + s) * KVV
                                            : g_cnew + b * KVV;
        cp_async16(sb + (unsigned)(STGO + s * 36 + kq * 4) * 4u, row + kq * 4);
    }
    cp_commit();

    float2 acc[8][4];
    #pragma unroll
    for (int i = 0; i < 8; i++)
        #pragma unroll
        for (int j = 0; j < 4; j++) acc[i][j] = make_float2(0.f, 0.f);

    for (int hk = 0; hk < 16; hk++) {
        int kb = hk * 32;
        asm volatile("cp.async.wait_group 0;");
        __syncthreads();                       // stage ready; prev compute done
        // transpose stage[s][36] -> cs[hk&1][k][512]
        {
            const float* st = sm + STGO + tid * 36;
            float* cs = sm + ((hk & 1) ? CS1 : CS0);
            #pragma unroll
            for (int q = 0; q < 8; q++) {
                float4 v = *(const float4*)(st + q * 4);
                cs[(q * 4 + 0) * 512 + tid] = v.x;
                cs[(q * 4 + 1) * 512 + tid] = v.y;
                cs[(q * 4 + 2) * 512 + tid] = v.z;
                cs[(q * 4 + 3) * 512 + tid] = v.w;
            }
        }
        // q chunk (scalar): warp w handles h = w, w+16; lane = k  (coalesced LDG)
        {
            float* qd = sm + ((hk & 1) ? QD1 : QD0);
            #pragma unroll
            for (int t = 0; t < 2; t++) {
                int h = w + t * 16;
                qd[lane * 36 + h] = g_qabs[((size_t)b * HH + h) * KVV + kb + lane];
            }
        }
        __syncthreads();                       // transpose reads done; cs/qd visible
        if (hk < 15) {                         // stage now free -> issue next chunk
            int kb2 = kb + 32;
            #pragma unroll
            for (int j = 0; j < 8; j++) {
                int i = tid + j * 512;
                int s = i >> 3, kq = i & 7;
                const float* row = (S0 + s < PASTN) ? past_c + ((size_t)b * PASTN + S0 + s) * KVV
                                                    : g_cnew + b * KVV;
                cp_async16(sb + (unsigned)(STGO + s * 36 + kq * 4) * 4u, row + kb2 + kq * 4);
            }
            cp_commit();
        }
        // compute (16 k per warp via kgrp)
        {
            const float* cs = sm + ((hk & 1) ? CS1 : CS0);
            const float* qd = sm + ((hk & 1) ? QD1 : QD0);
            int sp = sgrp * 256 + lane * 2;
            #pragma unroll 2
            for (int k = kgrp * 16; k < kgrp * 16 + 16; k++) {
                float4 qa = *(const float4*)(qd + k * 36 + hgrp * 8);
                float4 qb = *(const float4*)(qd + k * 36 + hgrp * 8 + 4);
                float2 c2[4];
                #pragma unroll
                for (int j = 0; j < 4; j++)
                    c2[j] = *(const float2*)&cs[k * 512 + sp + j * 64];
                #pragma unroll
                for (int j = 0; j < 4; j++) {
                    acc[0][j] = ffma2s(qa.x, c2[j], acc[0][j]);
                    acc[1][j] = ffma2s(qa.y, c2[j], acc[1][j]);
                    acc[2][j] = ffma2s(qa.z, c2[j], acc[2][j]);
                    acc[3][j] = ffma2s(qa.w, c2[j], acc[3][j]);
                    acc[4][j] = ffma2s(qb.x, c2[j], acc[4][j]);
                    acc[5][j] = ffma2s(qb.y, c2[j], acc[5][j]);
                    acc[6][j] = ffma2s(qb.z, c2[j], acc[6][j]);
                    acc[7][j] = ffma2s(qb.w, c2[j], acc[7][j]);
                }
            }
        }
    }
    // cross-kgrp reduction through smem (reuse cs0 region), then store
    __syncthreads();
    float2* red = (float2*)sm;
    int wid8 = hgrp * 2 + sgrp;
    if (kgrp == 1) {
        #pragma unroll
        for (int i = 0; i < 8; i++)
            #pragma unroll
            for (int j = 0; j < 4; j++)
                red[((wid8 * 32 + lane) * 8 + i) * 4 + j] = acc[i][j];
    }
    __syncthreads();
    if (kgrp == 0) {
        #pragma unroll
        for (int i = 0; i < 8; i++)
            #pragma unroll
            for (int j = 0; j < 4; j++) {
                float2 p = red[((wid8 * 32 + lane) * 8 + i) * 4 + j];
                acc[i][j].x += p.x; acc[i][j].y += p.y;
                *(float2*)&g_scores[((size_t)b * HH + hgrp * 8 + i) * TOTALN
                                    + S0 + sgrp * 256 + lane * 2 + j * 64] = acc[i][j];
            }
    }
}

// ---------------- K4: row stats (m, 1/l) per (b,h) ----------------
__global__ __launch_bounds__(256) void k_mrow() {
    int bh = blockIdx.x;
    int tid = threadIdx.x;
    int w = tid >> 5, lane = tid & 31;
    const float* row = g_scores + (size_t)bh * TOTALN;
    float4 v[8];
    #pragma unroll
    for (int i = 0; i < 8; i++) v[i] = ((const float4*)row)[tid * 8 + i];
    float m = -1e30f;
    #pragma unroll
    for (int i = 0; i < 8; i++)
        m = fmaxf(m, fmaxf(fmaxf(v[i].x, v[i].y), fmaxf(v[i].z, v[i].w)));
    #pragma unroll
    for (int o = 16; o; o >>= 1) m = fmaxf(m, __shfl_xor_sync(0xffffffffu, m, o));
    __shared__ float redm[8], reds[8];
    if (lane == 0) redm[w] = m;
    __syncthreads();
    m = redm[0];
    #pragma unroll
    for (int i = 1; i < 8; i++) m = fmaxf(m, redm[i]);
    float s = 0.f;
    #pragma unroll
    for (int i = 0; i < 8; i++)
        s += __expf(v[i].x - m) + __expf(v[i].y - m) + __expf(v[i].z - m) + __expf(v[i].w - m);
    #pragma unroll
    for (int o = 16; o; o >>= 1) s += __shfl_xor_sync(0xffffffffu, s, o);
    if (lane == 0) reds[w] = s;
    __syncthreads();
    if (tid == 0) {
        s = reds[0] + reds[1] + reds[2] + reds[3] + reds[4] + reds[5] + reds[6] + reds[7];
        g_ml2[bh * 2 + 0] = m;
        g_ml2[bh * 2 + 1] = 1.f / s;
    }
}

// ---------------- K5: o_c partials — R7 shape (512 thr, 16x8 grid) + scalar-attn smem ----------------
// warp = (hgrp[4] x ngrp[2] x sgrp[2]).
// smem: cb[2][32s][512n] @0 (32768 fl); ad scalar [32s][36] @32768 (1152 fl).
#define ADOFF 32768
#define SMEM_OV ((32768 + 1152) * 4)

__global__ __launch_bounds__(512) void k_ov(const float* __restrict__ past_c) {
    extern __shared__ float sm[];
    __shared__ float msh[HH], ilsh[HH];
    int sc = blockIdx.x, b = blockIdx.y;
    int tid = threadIdx.x;
    unsigned sb;
    asm("{.reg .u64 t; cvta.to.shared.u64 t, %1; cvt.u32.u64 %0, t;}" : "=r"(sb) : "l"(sm));
    int S0 = sc * 512;
    int w = tid >> 5, lane = tid & 31;
    int hgrp = w >> 2, ngrp = (w >> 1) & 1, sgrp = w & 1;
    if (tid < HH) {
        msh[tid]  = g_ml2[(b * HH + tid) * 2 + 0];
        ilsh[tid] = g_ml2[(b * HH + tid) * 2 + 1];
    }
    float2 acc[8][4];
    #pragma unroll
    for (int i = 0; i < 8; i++)
        #pragma unroll
        for (int j = 0; j < 4; j++) acc[i][j] = make_float2(0.f, 0.f);

    // prologue: issue chunk 0
    #pragma unroll
    for (int t = 0; t < 8; t++) {
        int i = tid + t * 512;
        int s = i >> 7, n4 = i & 127;
        const float* row = (S0 + s < PASTN) ? past_c + ((size_t)b * PASTN + S0 + s) * KVV
                                            : g_cnew + b * KVV;
        cp_async16(sb + (unsigned)(s * 512 + n4 * 4) * 4u, row + n4 * 4);
    }
    cp_commit();

    float* ad = sm + ADOFF;
    for (int ch = 0; ch < 16; ch++) {
        int s0 = S0 + ch * 32;
        asm volatile("cp.async.wait_group 0;");
        __syncthreads();                   // chunk ch visible; compute(ch-1) done
        // ad fill (scalar): warp w handles h = w, w+16; lane = s  (coalesced LDG)
        #pragma unroll
        for (int t = 0; t < 2; t++) {
            int h = w + t * 16;
            float e = __expf(g_scores[((size_t)b * HH + h) * TOTALN + s0 + lane] - msh[h]) * ilsh[h];
            ad[lane * 36 + h] = e;
        }
        if (ch < 15) {                     // issue next into buffer (ch+1)&1 (safe: last reader synced)
            int s0n = s0 + 32;
            int base = ((ch + 1) & 1) * 16384;
            #pragma unroll
            for (int t = 0; t < 8; t++) {
                int i = tid + t * 512;
                int s = i >> 7, n4 = i & 127;
                const float* row = (s0n + s < PASTN) ? past_c + ((size_t)b * PASTN + s0n + s) * KVV
                                                     : g_cnew + b * KVV;
                cp_async16(sb + (unsigned)(base + s * 512 + n4 * 4) * 4u, row + n4 * 4);
            }
            cp_commit();
        }
        __syncthreads();                   // ad visible
        const float* c_s = sm + (ch & 1) * 16384;
        #pragma unroll 2
        for (int s = sgrp * 16; s < sgrp * 16 + 16; s++) {
            float4 aa = *(const float4*)(ad + s * 36 + hgrp * 8);
            float4 ab = *(const float4*)(ad + s * 36 + hgrp * 8 + 4);
            float2 c2[4];
            #pragma unroll
            for (int j = 0; j < 4; j++)
                c2[j] = *(const float2*)&c_s[s * 512 + (ngrp * 128 + j * 32 + lane) * 2];
            #pragma unroll
            for (int j = 0; j < 4; j++) {
                acc[0][j] = ffma2s(aa.x, c2[j], acc[0][j]);
                acc[1][j] = ffma2s(aa.y, c2[j], acc[1][j]);
                acc[2][j] = ffma2s(aa.z, c2[j], acc[2][j]);
                acc[3][j] = ffma2s(aa.w, c2[j], acc[3][j]);
                acc[4][j] = ffma2s(ab.x, c2[j], acc[4][j]);
                acc[5][j] = ffma2s(ab.y, c2[j], acc[5][j]);
                acc[6][j] = ffma2s(ab.z, c2[j], acc[6][j]);
                acc[7][j] = ffma2s(ab.w, c2[j], acc[7][j]);
            }
        }
    }
    // cross-sgrp reduction (reuse cb[0] region), then store
    __syncthreads();
    float2* red = (float2*)sm;
    int wid8 = hgrp * 2 + ngrp;
    if (sgrp == 1) {
        #pragma unroll
        for (int i = 0; i < 8; i++)
            #pragma unroll
            for (int j = 0; j < 4; j++)
                red[((wid8 * 32 + lane) * 8 + i) * 4 + j] = acc[i][j];
    }
    __syncthreads();
    if (sgrp == 0) {
        #pragma unroll
        for (int i = 0; i < 8; i++)
            #pragma unroll
            for (int j = 0; j < 4; j++) {
                float2 p = red[((wid8 * 32 + lane) * 8 + i) * 4 + j];
                acc[i][j].x += p.x; acc[i][j].y += p.y;
                *(float2*)&g_opart[(((size_t)sc * BB + b) * HH + hgrp * 8 + i) * KVV
                                   + (ngrp * 128 + j * 32 + lane) * 2] = acc[i][j];
            }
    }
}

// reduce NSC s-partials -> g_oc
__global__ void k_redo() {
    int i = blockIdx.x * 256 + threadIdx.x;
    const float4* p = (const float4*)g_opart;
    float4 s = make_float4(0.f, 0.f, 0.f, 0.f);
    #pragma unroll
    for (int c = 0; c < NSC; c++) {
        float4 t = p[c * 32768 + i];
        s.x += t.x; s.y += t.y; s.z += t.z; s.w += t.w;
    }
    ((float4*)g_oc)[i] = s;
}

// ---------------- K6: per-head v-up (n-split, atomic) ----------------
__global__ __launch_bounds__(128) void k_vup(const float* __restrict__ wv) {
    __shared__ float od[128][9];   // [n_local][b] scalar
    int h = blockIdx.x, nc = blockIdx.y;
    int tid = threadIdx.x;
    int jp = tid & 63, g = tid >> 6;
    for (int i = tid; i < 1024; i += 128) {
        int n = i >> 3, b = i & 7;
        od[n][b] = g_oc[((size_t)b * HH + h) * KVV + nc * 128 + n];
    }
    __syncthreads();
    float2 acc[BB];
    #pragma unroll
    for (int b = 0; b < BB; b++) acc[b] = make_float2(0.f, 0.f);
    const float* wp = wv + (size_t)(nc * 128 + g * 64) * (HH * HDD) + h * HDD + jp * 2;
    #pragma unroll 8
    for (int n = 0; n < 64; n++) {
        float2 w2 = *(const float2*)(wp + (size_t)n * (HH * HDD));
        float4 o0 = *(const float4*)&od[g * 64 + n][0];
        float4 o1 = *(const float4*)&od[g * 64 + n][4];
        acc[0] = ffma2s(o0.x, w2, acc[0]);
        acc[1] = ffma2s(o0.y, w2, acc[1]);
        acc[2] = ffma2s(o0.z, w2, acc[2]);
        acc[3] = ffma2s(o0.w, w2, acc[3]);
        acc[4] = ffma2s(o1.x, w2, acc[4]);
        acc[5] = ffma2s(o1.y, w2, acc[5]);
        acc[6] = ffma2s(o1.z, w2, acc[6]);
        acc[7] = ffma2s(o1.w, w2, acc[7]);
    }
    #pragma unroll
    for (int b = 0; b < BB; b++) {
        atomicAdd(&g_ohead[b * DD + h * HDD + jp * 2 + 0], acc[b].x);
        atomicAdd(&g_ohead[b * DD + h * HDD + jp * 2 + 1], acc[b].y);
    }
}

// ---------------- K7: out = out_head @ w_o (m-split over 16, atomic) ----------------
__global__ __launch_bounds__(128) void k_oproj(const float* __restrict__ wo,
                                               float* __restrict__ out) {
    __shared__ float ohd[256][9];   // [m_local][b] scalar
    int dt = blockIdx.x, mc = blockIdx.y;
    int tid = threadIdx.x;
    for (int i = tid; i < 2048; i += 128) {
        int m = i >> 3, b = i & 7;
        ohd[m][b] = g_ohead[b * DD + mc * 256 + m];
    }
    __syncthreads();
    float2 acc[BB];
    #pragma unroll
    for (int b = 0; b < BB; b++) acc[b] = make_float2(0.f, 0.f);
    const float* wp = wo + (size_t)mc * 256 * DD + dt * 256 + tid * 2;
    #pragma unroll 8
    for (int m = 0; m < 256; m++) {
        float2 w2 = *(const float2*)(wp + (size_t)m * DD);
        float4 o0 = *(const float4*)&ohd[m][0];
        float4 o1 = *(const float4*)&ohd[m][4];
        acc[0] = ffma2s(o0.x, w2, acc[0]);
        acc[1] = ffma2s(o0.y, w2, acc[1]);
        acc[2] = ffma2s(o0.z, w2, acc[2]);
        acc[3] = ffma2s(o0.w, w2, acc[3]);
        acc[4] = ffma2s(o1.x, w2, acc[4]);
        acc[5] = ffma2s(o1.y, w2, acc[5]);
        acc[6] = ffma2s(o1.z, w2, acc[6]);
        acc[7] = ffma2s(o1.w, w2, acc[7]);
    }
    #pragma unroll
    for (int b = 0; b < BB; b++) {
        atomicAdd(&out[b * DD + dt * 256 + tid * 2 + 0], acc[b].x);
        atomicAdd(&out[b * DD + dt * 256 + tid * 2 + 1], acc[b].y);
    }
}

// ---------------- launch ----------------
extern "C" void kernel_launch(void* const* d_in, const int* in_sizes, int n_in,
                              void* d_out, int out_size) {
    const float* x      = (const float*)d_in[0];
    const float* past_c = (const float*)d_in[1];
    const float* aqk    = (const float*)d_in[2];
    const float* wc     = (const float*)d_in[3];
    const float* wv     = (const float*)d_in[4];
    const float* wo     = (const float*)d_in[5];
    float* out = (float*)d_out;

    cudaFuncSetAttribute(k_scores, cudaFuncAttributeMaxDynamicSharedMemorySize, SMEM_SC);
    cudaFuncSetAttribute(k_ov,     cudaFuncAttributeMaxDynamicSharedMemorySize, SMEM_OV);

    k_init<<<512, 256>>>(out);                          // idx 0
    k_compress<<<32, 256>>>(x, wc);                     // idx 1
    k_qabs<<<dim3(NKC, 32), 128>>>(x, aqk);             // idx 2
    k_scores<<<dim3(16, 8), 512, SMEM_SC>>>(past_c);    // idx 3  <- profiled
    k_mrow<<<256, 256>>>();                             // idx 4
    k_ov<<<dim3(NSC, 8), 512, SMEM_OV>>>(past_c);       // idx 5
    k_redo<<<128, 256>>>();                             // idx 6
    k_vup<<<dim3(32, 4), 128>>>(wv);                    // idx 7
    k_oproj<<<dim3(16, 16), 128>>>(wo, out);            // idx 8
}

// round 13
// speedup vs baseline: 1.1039x; 1.0203x over previous
#include <cuda_runtime.h>
#include <cuda_bf16.h>

#define BB 8
#define DD 4096
#define HH 32
#define HDD 128
#define KVV 512
#define PASTN 8191
#define TOTALN 8192
#define SCALEF 0.08838834764831845f  // 128^-0.5
#define NSC 16   // s-splits for k_ov
#define NKC 16   // k-splits for qabs

// ---------------- scratch ----------------
__device__ float g_cnew[BB * KVV];
__device__ float g_qabs[BB * HH * KVV];        // zero-init, atomic accumulate
__device__ float g_scores[BB * HH * TOTALN];
__device__ float g_ml2[BB * HH * 2];           // (rowmax, 1/rowsum)
__device__ float g_opart[NSC * BB * HH * KVV];
__device__ float g_oc[BB * HH * KVV];
__device__ float g_ohead[BB * HH * HDD];

// packed dual-fp32 FMA (sm_100+)
__device__ __forceinline__ float2 ffma2(const float2 a, const float2 b, const float2 c) {
    float2 d;
    asm("fma.rn.f32x2 %0, %1, %2, %3;"
        : "=l"(*(unsigned long long*)&d)
        : "l"(*(const unsigned long long*)&a),
          "l"(*(const unsigned long long*)&b),
          "l"(*(const unsigned long long*)&c));
    return d;
}
__device__ __forceinline__ float2 ffma2s(const float a, const float2 b, const float2 c) {
    return ffma2(make_float2(a, a), b, c);
}

__device__ __forceinline__ void cp_async16(unsigned s, const void* g) {
    asm volatile("cp.async.cg.shared.global [%0], [%1], 16;" :: "r"(s), "l"(g));
}
__device__ __forceinline__ void cp_commit() {
    asm volatile("cp.async.commit_group;");
}
__device__ __forceinline__ unsigned smaddr(const void* p) {
    unsigned a;
    asm("{.reg .u64 t; cvta.to.shared.u64 t, %1; cvt.u32.u64 %0, t;}" : "=r"(a) : "l"(p));
    return a;
}

// fp32 -> packed bf16 hi/lo pair (hi = rn(x), lo = rn(x - hi))
__device__ __forceinline__ void cvt_hilo(float2 v, unsigned& hi, unsigned& lo) {
    __nv_bfloat16 h0 = __float2bfloat16_rn(v.x);
    __nv_bfloat16 h1 = __float2bfloat16_rn(v.y);
    __nv_bfloat16 l0 = __float2bfloat16_rn(v.x - __bfloat162float(h0));
    __nv_bfloat16 l1 = __float2bfloat16_rn(v.y - __bfloat162float(h1));
    hi = (unsigned)__bfloat16_as_ushort(h0) | ((unsigned)__bfloat16_as_ushort(h1) << 16);
    lo = (unsigned)__bfloat16_as_ushort(l0) | ((unsigned)__bfloat16_as_ushort(l1) << 16);
}

// classic tensor-core mma (sm_80+ PTX, legal on compute_103)
__device__ __forceinline__ void mma16816(float* d, const unsigned* a, const unsigned* b) {
    asm volatile(
        "mma.sync.aligned.m16n8k16.row.col.f32.bf16.bf16.f32 "
        "{%0,%1,%2,%3}, {%4,%5,%6,%7}, {%8,%9}, {%0,%1,%2,%3};"
        : "+f"(d[0]), "+f"(d[1]), "+f"(d[2]), "+f"(d[3])
        : "r"(a[0]), "r"(a[1]), "r"(a[2]), "r"(a[3]), "r"(b[0]), "r"(b[1]));
}

// ---------------- K0: zero d_out, g_cnew, g_ohead, g_qabs ----------------
__global__ void k_init(float* __restrict__ out) {
    int i = blockIdx.x * 256 + threadIdx.x;       // 131072 threads
    g_qabs[i] = 0.f;
    if (i < BB * DD) { out[i] = 0.f; g_ohead[i] = 0.f; }
    if (i < BB * KVV) g_cnew[i] = 0.f;
}

// ---------------- K1: c_new = x @ w_compress (k-split, atomic) ----------------
__global__ __launch_bounds__(256) void k_compress(const float* __restrict__ x,
                                                  const float* __restrict__ wc) {
    __shared__ float xs[128][9];
    int kc = blockIdx.x;
    int tid = threadIdx.x;
    for (int i = tid; i < 1024; i += 256) {
        int k = i >> 3, b = i & 7;
        xs[k][b] = x[b * DD + kc * 128 + k];
    }
    __syncthreads();
    float2 acc[BB];
    #pragma unroll
    for (int b = 0; b < BB; b++) acc[b] = make_float2(0.f, 0.f);
    const float* wp = wc + (size_t)kc * 128 * KVV + tid * 2;
    #pragma unroll 8
    for (int k = 0; k < 128; k++) {
        float2 w2 = *(const float2*)(wp + (size_t)k * KVV);
        float4 x0 = *(const float4*)&xs[k][0];
        float4 x1 = *(const float4*)&xs[k][4];
        acc[0] = ffma2s(x0.x, w2, acc[0]);
        acc[1] = ffma2s(x0.y, w2, acc[1]);
        acc[2] = ffma2s(x0.z, w2, acc[2]);
        acc[3] = ffma2s(x0.w, w2, acc[3]);
        acc[4] = ffma2s(x1.x, w2, acc[4]);
        acc[5] = ffma2s(x1.y, w2, acc[5]);
        acc[6] = ffma2s(x1.z, w2, acc[6]);
        acc[7] = ffma2s(x1.w, w2, acc[7]);
    }
    #pragma unroll
    for (int b = 0; b < BB; b++) {
        atomicAdd(&g_cnew[b * KVV + tid * 2 + 0], acc[b].x);
        atomicAdd(&g_cnew[b * KVV + tid * 2 + 1], acc[b].y);
    }
}

// ---------------- K2: q_abs (scale folded into x), atomic accumulate ----------------
__global__ __launch_bounds__(128) void k_qabs(const float* __restrict__ x,
                                              const float* __restrict__ aqk) {
    __shared__ float xs[256][9];
    int kc = blockIdx.x;
    int h  = blockIdx.y;
    int tid = threadIdx.x;
    for (int i = tid; i < 2048; i += 128) {
        int k = i >> 3, b = i & 7;
        xs[k][b] = x[b * DD + kc * 256 + k] * SCALEF;
    }
    __syncthreads();
    float2 acc[BB][2];
    #pragma unroll
    for (int b = 0; b < BB; b++) {
        acc[b][0] = make_float2(0.f, 0.f);
        acc[b][1] = make_float2(0.f, 0.f);
    }
    const float* ap = aqk + ((size_t)h * DD + (size_t)kc * 256) * KVV + tid * 4;
    #pragma unroll 8
    for (int k = 0; k < 256; k++) {
        float4 a4 = *(const float4*)(ap + (size_t)k * KVV);
        float2 alo = make_float2(a4.x, a4.y);
        float2 ahi = make_float2(a4.z, a4.w);
        float4 x0 = *(const float4*)&xs[k][0];
        float4 x1 = *(const float4*)&xs[k][4];
        acc[0][0] = ffma2s(x0.x, alo, acc[0][0]); acc[0][1] = ffma2s(x0.x, ahi, acc[0][1]);
        acc[1][0] = ffma2s(x0.y, alo, acc[1][0]); acc[1][1] = ffma2s(x0.y, ahi, acc[1][1]);
        acc[2][0] = ffma2s(x0.z, alo, acc[2][0]); acc[2][1] = ffma2s(x0.z, ahi, acc[2][1]);
        acc[3][0] = ffma2s(x0.w, alo, acc[3][0]); acc[3][1] = ffma2s(x0.w, ahi, acc[3][1]);
        acc[4][0] = ffma2s(x1.x, alo, acc[4][0]); acc[4][1] = ffma2s(x1.x, ahi, acc[4][1]);
        acc[5][0] = ffma2s(x1.y, alo, acc[5][0]); acc[5][1] = ffma2s(x1.y, ahi, acc[5][1]);
        acc[6][0] = ffma2s(x1.z, alo, acc[6][0]); acc[6][1] = ffma2s(x1.z, ahi, acc[6][1]);
        acc[7][0] = ffma2s(x1.w, alo, acc[7][0]); acc[7][1] = ffma2s(x1.w, ahi, acc[7][1]);
    }
    #pragma unroll
    for (int b = 0; b < BB; b++) {
        float* dst = &g_qabs[((size_t)b * HH + h) * KVV + tid * 4];
        atomicAdd(dst + 0, acc[b][0].x);
        atomicAdd(dst + 1, acc[b][0].y);
        atomicAdd(dst + 2, acc[b][1].x);
        atomicAdd(dst + 3, acc[b][1].y);
    }
}

// ---------------- K3: scores via mma.sync bf16 3-split ----------------
// grid (sc=16, b=8); 512 threads = 16 warps; warp owns 32s x 32h tile.
// smem (floats): stage[2][512][36] @0/@18432; q fp32 [32][516] @36864.
#define SG_STG0 0
#define SG_STG1 18432
#define SG_Q 36864
#define QSTR 516
#define SMEM_SC ((36864 + 32 * QSTR) * 4)   // 213504 B

__device__ __forceinline__ void sc_issue(unsigned sb, const float* __restrict__ past_c,
                                         int b, int S0, int ck, int stg, int tid) {
    #pragma unroll
    for (int t = 0; t < 8; t++) {
        int i = tid + t * 512;
        int s = i >> 3, seg = i & 7;
        const float* row = (S0 + s < PASTN) ? past_c + ((size_t)b * PASTN + S0 + s) * KVV
                                            : g_cnew + b * KVV;
        cp_async16(sb + (unsigned)(stg + s * 36 + seg * 4) * 4u, row + ck * 32 + seg * 4);
    }
    cp_commit();
}

__global__ __launch_bounds__(512) void k_scores(const float* __restrict__ past_c) {
    extern __shared__ float sm[];
    unsigned sb = smaddr(sm);
    int sc = blockIdx.x, b = blockIdx.y;
    int tid = threadIdx.x;
    int w = tid >> 5, lane = tid & 31;
    int gid = lane >> 2, tig = lane & 3;
    int S0 = sc * 512;
    int SB = w * 32;
    float* qs = sm + SG_Q;

    // q fill (fp32, scale already applied): 4096 float4
    #pragma unroll
    for (int t = 0; t < 8; t++) {
        int i = tid + t * 512;
        int h = i >> 7, j = i & 127;
        *(float4*)&qs[h * QSTR + j * 4] = *(const float4*)&g_qabs[((size_t)b * HH + h) * KVV + j * 4];
    }
    // prologue: chunk 0
    sc_issue(sb, past_c, b, S0, 0, SG_STG0, tid);

    float d[2][4][4];
    #pragma unroll
    for (int m = 0; m < 2; m++)
        #pragma unroll
        for (int n = 0; n < 4; n++)
            #pragma unroll
            for (int c = 0; c < 4; c++) d[m][n][c] = 0.f;

    for (int ck = 0; ck < 16; ck++) {
        asm volatile("cp.async.wait_group 0;");
        __syncthreads();                       // chunk ck visible; prev compute done
        if (ck < 15)
            sc_issue(sb, past_c, b, S0, ck + 1, ((ck + 1) & 1) ? SG_STG1 : SG_STG0, tid);
        const float* A = sm + ((ck & 1) ? SG_STG1 : SG_STG0);
        #pragma unroll
        for (int ks = 0; ks < 2; ks++) {
            int k0 = ks * 16;
            unsigned ahi[2][4], alo[2][4], bhi[4][2], blo[4][2];
            #pragma unroll
            for (int m = 0; m < 2; m++) {
                const float* Ar = A + (SB + m * 16 + gid) * 36 + k0 + tig * 2;
                cvt_hilo(*(const float2*)(Ar),            ahi[m][0], alo[m][0]);
                cvt_hilo(*(const float2*)(Ar + 8 * 36),   ahi[m][1], alo[m][1]);
                cvt_hilo(*(const float2*)(Ar + 8),        ahi[m][2], alo[m][2]);
                cvt_hilo(*(const float2*)(Ar + 8 * 36 + 8), ahi[m][3], alo[m][3]);
            }
            #pragma unroll
            for (int n = 0; n < 4; n++) {
                const float* Br = qs + (n * 8 + gid) * QSTR + ck * 32 + k0 + tig * 2;
                cvt_hilo(*(const float2*)(Br),     bhi[n][0], blo[n][0]);
                cvt_hilo(*(const float2*)(Br + 8), bhi[n][1], blo[n][1]);
            }
            #pragma unroll
            for (int m = 0; m < 2; m++)
                #pragma unroll
                for (int n = 0; n < 4; n++) {
                    mma16816(d[m][n], ahi[m], bhi[n]);
                    mma16816(d[m][n], ahi[m], blo[n]);
                    mma16816(d[m][n], alo[m], bhi[n]);
                }
        }
    }

    // epilogue: stage D through smem (warp-private region in stage0), coalesced store
    __syncthreads();
    float* outw = sm + SG_STG0 + w * (32 * 33);
    #pragma unroll
    for (int m = 0; m < 2; m++)
        #pragma unroll
        for (int n = 0; n < 4; n++)
            #pragma unroll
            for (int c = 0; c < 4; c++) {
                int srow = m * 16 + gid + ((c >> 1) << 3);
                int hcol = n * 8 + tig * 2 + (c & 1);
                outw[hcol * 33 + srow] = d[m][n][c];
            }
    __syncwarp();
    #pragma unroll
    for (int h = 0; h < 32; h++)
        g_scores[((size_t)b * HH + h) * TOTALN + S0 + SB + lane] = outw[h * 33 + lane];
}

// ---------------- K4: row stats (m, 1/l) per (b,h) ----------------
__global__ __launch_bounds__(256) void k_mrow() {
    int bh = blockIdx.x;
    int tid = threadIdx.x;
    int w = tid >> 5, lane = tid & 31;
    const float* row = g_scores + (size_t)bh * TOTALN;
    float4 v[8];
    #pragma unroll
    for (int i = 0; i < 8; i++) v[i] = ((const float4*)row)[tid * 8 + i];
    float m = -1e30f;
    #pragma unroll
    for (int i = 0; i < 8; i++)
        m = fmaxf(m, fmaxf(fmaxf(v[i].x, v[i].y), fmaxf(v[i].z, v[i].w)));
    #pragma unroll
    for (int o = 16; o; o >>= 1) m = fmaxf(m, __shfl_xor_sync(0xffffffffu, m, o));
    __shared__ float redm[8], reds[8];
    if (lane == 0) redm[w] = m;
    __syncthreads();
    m = redm[0];
    #pragma unroll
    for (int i = 1; i < 8; i++) m = fmaxf(m, redm[i]);
    float s = 0.f;
    #pragma unroll
    for (int i = 0; i < 8; i++)
        s += __expf(v[i].x - m) + __expf(v[i].y - m) + __expf(v[i].z - m) + __expf(v[i].w - m);
    #pragma unroll
    for (int o = 16; o; o >>= 1) s += __shfl_xor_sync(0xffffffffu, s, o);
    if (lane == 0) reds[w] = s;
    __syncthreads();
    if (tid == 0) {
        s = reds[0] + reds[1] + reds[2] + reds[3] + reds[4] + reds[5] + reds[6] + reds[7];
        g_ml2[bh * 2 + 0] = m;
        g_ml2[bh * 2 + 1] = 1.f / s;
    }
}

// ---------------- K5: o_c partials — 512 thr, split-s + scalar-attn smem ----------------
#define ADOFF 32768
#define SMEM_OV ((32768 + 1152) * 4)

__global__ __launch_bounds__(512) void k_ov(const float* __restrict__ past_c) {
    extern __shared__ float sm[];
    __shared__ float msh[HH], ilsh[HH];
    int sc = blockIdx.x, b = blockIdx.y;
    int tid = threadIdx.x;
    unsigned sb = smaddr(sm);
    int S0 = sc * 512;
    int w = tid >> 5, lane = tid & 31;
    int hgrp = w >> 2, ngrp = (w >> 1) & 1, sgrp = w & 1;
    if (tid < HH) {
        msh[tid]  = g_ml2[(b * HH + tid) * 2 + 0];
        ilsh[tid] = g_ml2[(b * HH + tid) * 2 + 1];
    }
    float2 acc[8][4];
    #pragma unroll
    for (int i = 0; i < 8; i++)
        #pragma unroll
        for (int j = 0; j < 4; j++) acc[i][j] = make_float2(0.f, 0.f);

    #pragma unroll
    for (int t = 0; t < 8; t++) {
        int i = tid + t * 512;
        int s = i >> 7, n4 = i & 127;
        const float* row = (S0 + s < PASTN) ? past_c + ((size_t)b * PASTN + S0 + s) * KVV
                                            : g_cnew + b * KVV;
        cp_async16(sb + (unsigned)(s * 512 + n4 * 4) * 4u, row + n4 * 4);
    }
    cp_commit();

    float* ad = sm + ADOFF;
    for (int ch = 0; ch < 16; ch++) {
        int s0 = S0 + ch * 32;
        asm volatile("cp.async.wait_group 0;");
        __syncthreads();
        #pragma unroll
        for (int t = 0; t < 2; t++) {
            int h = w + t * 16;
            float e = __expf(g_scores[((size_t)b * HH + h) * TOTALN + s0 + lane] - msh[h]) * ilsh[h];
            ad[lane * 36 + h] = e;
        }
        if (ch < 15) {
            int s0n = s0 + 32;
            int base = ((ch + 1) & 1) * 16384;
            #pragma unroll
            for (int t = 0; t < 8; t++) {
                int i = tid + t * 512;
                int s = i >> 7, n4 = i & 127;
                const float* row = (s0n + s < PASTN) ? past_c + ((size_t)b * PASTN + s0n + s) * KVV
                                                     : g_cnew + b * KVV;
                cp_async16(sb + (unsigned)(base + s * 512 + n4 * 4) * 4u, row + n4 * 4);
            }
            cp_commit();
        }
        __syncthreads();
        const float* c_s = sm + (ch & 1) * 16384;
        #pragma unroll 2
        for (int s = sgrp * 16; s < sgrp * 16 + 16; s++) {
            float4 aa = *(const float4*)(ad + s * 36 + hgrp * 8);
            float4 ab = *(const float4*)(ad + s * 36 + hgrp * 8 + 4);
            float2 c2[4];
            #pragma unroll
            for (int j = 0; j < 4; j++)
                c2[j] = *(const float2*)&c_s[s * 512 + (ngrp * 128 + j * 32 + lane) * 2];
            #pragma unroll
            for (int j = 0; j < 4; j++) {
                acc[0][j] = ffma2s(aa.x, c2[j], acc[0][j]);
                acc[1][j] = ffma2s(aa.y, c2[j], acc[1][j]);
                acc[2][j] = ffma2s(aa.z, c2[j], acc[2][j]);
                acc[3][j] = ffma2s(aa.w, c2[j], acc[3][j]);
                acc[4][j] = ffma2s(ab.x, c2[j], acc[4][j]);
                acc[5][j] = ffma2s(ab.y, c2[j], acc[5][j]);
                acc[6][j] = ffma2s(ab.z, c2[j], acc[6][j]);
                acc[7][j] = ffma2s(ab.w, c2[j], acc[7][j]);
            }
        }
    }
    __syncthreads();
    float2* red = (float2*)sm;
    int wid8 = hgrp * 2 + ngrp;
    if (sgrp == 1) {
        #pragma unroll
        for (int i = 0; i < 8; i++)
            #pragma unroll
            for (int j = 0; j < 4; j++)
                red[((wid8 * 32 + lane) * 8 + i) * 4 + j] = acc[i][j];
    }
    __syncthreads();
    if (sgrp == 0) {
        #pragma unroll
        for (int i = 0; i < 8; i++)
            #pragma unroll
            for (int j = 0; j < 4; j++) {
                float2 p = red[((wid8 * 32 + lane) * 8 + i) * 4 + j];
                acc[i][j].x += p.x; acc[i][j].y += p.y;
                *(float2*)&g_opart[(((size_t)sc * BB + b) * HH + hgrp * 8 + i) * KVV
                                   + (ngrp * 128 + j * 32 + lane) * 2] = acc[i][j];
            }
    }
}

// reduce NSC s-partials -> g_oc
__global__ void k_redo() {
    int i = blockIdx.x * 256 + threadIdx.x;
    const float4* p = (const float4*)g_opart;
    float4 s = make_float4(0.f, 0.f, 0.f, 0.f);
    #pragma unroll
    for (int c = 0; c < NSC; c++) {
        float4 t = p[c * 32768 + i];
        s.x += t.x; s.y += t.y; s.z += t.z; s.w += t.w;
    }
    ((float4*)g_oc)[i] = s;
}

// ---------------- K6: per-head v-up (n-split, atomic) ----------------
__global__ __launch_bounds__(128) void k_vup(const float* __restrict__ wv) {
    __shared__ float od[128][9];
    int h = blockIdx.x, nc = blockIdx.y;
    int tid = threadIdx.x;
    int jp = tid & 63, g = tid >> 6;
    for (int i = tid; i < 1024; i += 128) {
        int n = i >> 3, b = i & 7;
        od[n][b] = g_oc[((size_t)b * HH + h) * KVV + nc * 128 + n];
    }
    __syncthreads();
    float2 acc[BB];
    #pragma unroll
    for (int b = 0; b < BB; b++) acc[b] = make_float2(0.f, 0.f);
    const float* wp = wv + (size_t)(nc * 128 + g * 64) * (HH * HDD) + h * HDD + jp * 2;
    #pragma unroll 8
    for (int n = 0; n < 64; n++) {
        float2 w2 = *(const float2*)(wp + (size_t)n * (HH * HDD));
        float4 o0 = *(const float4*)&od[g * 64 + n][0];
        float4 o1 = *(const float4*)&od[g * 64 + n][4];
        acc[0] = ffma2s(o0.x, w2, acc[0]);
        acc[1] = ffma2s(o0.y, w2, acc[1]);
        acc[2] = ffma2s(o0.z, w2, acc[2]);
        acc[3] = ffma2s(o0.w, w2, acc[3]);
        acc[4] = ffma2s(o1.x, w2, acc[4]);
        acc[5] = ffma2s(o1.y, w2, acc[5]);
        acc[6] = ffma2s(o1.z, w2, acc[6]);
        acc[7] = ffma2s(o1.w, w2, acc[7]);
    }
    #pragma unroll
    for (int b = 0; b < BB; b++) {
        atomicAdd(&g_ohead[b * DD + h * HDD + jp * 2 + 0], acc[b].x);
        atomicAdd(&g_ohead[b * DD + h * HDD + jp * 2 + 1], acc[b].y);
    }
}

// ---------------- K7: out = out_head @ w_o (m-split over 16, atomic) ----------------
__global__ __launch_bounds__(128) void k_oproj(const float* __restrict__ wo,
                                               float* __restrict__ out) {
    __shared__ float ohd[256][9];
    int dt = blockIdx.x, mc = blockIdx.y;
    int tid = threadIdx.x;
    for (int i = tid; i < 2048; i += 128) {
        int m = i >> 3, b = i & 7;
        ohd[m][b] = g_ohead[b * DD + mc * 256 + m];
    }
    __syncthreads();
    float2 acc[BB];
    #pragma unroll
    for (int b = 0; b < BB; b++) acc[b] = make_float2(0.f, 0.f);
    const float* wp = wo + (size_t)mc * 256 * DD + dt * 256 + tid * 2;
    #pragma unroll 8
    for (int m = 0; m < 256; m++) {
        float2 w2 = *(const float2*)(wp + (size_t)m * DD);
        float4 o0 = *(const float4*)&ohd[m][0];
        float4 o1 = *(const float4*)&ohd[m][4];
        acc[0] = ffma2s(o0.x, w2, acc[0]);
        acc[1] = ffma2s(o0.y, w2, acc[1]);
        acc[2] = ffma2s(o0.z, w2, acc[2]);
        acc[3] = ffma2s(o0.w, w2, acc[3]);
        acc[4] = ffma2s(o1.x, w2, acc[4]);
        acc[5] = ffma2s(o1.y, w2, acc[5]);
        acc[6] = ffma2s(o1.z, w2, acc[6]);
        acc[7] = ffma2s(o1.w, w2, acc[7]);
    }
    #pragma unroll
    for (int b = 0; b < BB; b++) {
        atomicAdd(&out[b * DD + dt * 256 + tid * 2 + 0], acc[b].x);
        atomicAdd(&out[b * DD + dt * 256 + tid * 2 + 1], acc[b].y);
    }
}

// ---------------- launch ----------------
extern "C" void kernel_launch(void* const* d_in, const int* in_sizes, int n_in,
                              void* d_out, int out_size) {
    const float* x      = (const float*)d_in[0];
    const float* past_c = (const float*)d_in[1];
    const float* aqk    = (const float*)d_in[2];
    const float* wc     = (const float*)d_in[3];
    const float* wv     = (const float*)d_in[4];
    const float* wo     = (const float*)d_in[5];
    float* out = (float*)d_out;

    cudaFuncSetAttribute(k_scores, cudaFuncAttributeMaxDynamicSharedMemorySize, SMEM_SC);
    cudaFuncSetAttribute(k_ov,     cudaFuncAttributeMaxDynamicSharedMemorySize, SMEM_OV);

    k_init<<<512, 256>>>(out);                          // idx 0
    k_compress<<<32, 256>>>(x, wc);                     // idx 1
    k_qabs<<<dim3(NKC, 32), 128>>>(x, aqk);             // idx 2
    k_scores<<<dim3(16, 8), 512, SMEM_SC>>>(past_c);    // idx 3  <- profiled
    k_mrow<<<256, 256>>>();                             // idx 4
    k_ov<<<dim3(NSC, 8), 512, SMEM_OV>>>(past_c);       // idx 5
    k_redo<<<128, 256>>>();                             // idx 6
    k_vup<<<dim3(32, 4), 128>>>(wv);                    // idx 7
    k_oproj<<<dim3(16, 16), 128>>>(wo, out);            // idx 8
}

// round 14
// speedup vs baseline: 1.2281x; 1.1125x over previous
#include <cuda_runtime.h>
#include <cuda_bf16.h>

#define BB 8
#define DD 4096
#define HH 32
#define HDD 128
#define KVV 512
#define PASTN 8191
#define TOTALN 8192
#define SCALEF 0.08838834764831845f  // 128^-0.5
#define NSC 16   // s-splits for k_ov
#define NKC 16   // k-splits for qabs

// ---------------- scratch ----------------
__device__ float g_cnew[BB * KVV];
__device__ float g_qabs[BB * HH * KVV];        // zero-init, atomic accumulate
__device__ float g_scores[BB * HH * TOTALN];
__device__ float g_ml2[BB * HH * 2];           // (rowmax, 1/rowsum)
__device__ float g_opart[NSC * BB * HH * KVV];
__device__ float g_oc[BB * HH * KVV];
__device__ float g_ohead[BB * HH * HDD];

// packed dual-fp32 FMA (sm_100+)
__device__ __forceinline__ float2 ffma2(const float2 a, const float2 b, const float2 c) {
    float2 d;
    asm("fma.rn.f32x2 %0, %1, %2, %3;"
        : "=l"(*(unsigned long long*)&d)
        : "l"(*(const unsigned long long*)&a),
          "l"(*(const unsigned long long*)&b),
          "l"(*(const unsigned long long*)&c));
    return d;
}
__device__ __forceinline__ float2 ffma2s(const float a, const float2 b, const float2 c) {
    return ffma2(make_float2(a, a), b, c);
}

__device__ __forceinline__ void cp_async16(unsigned s, const void* g) {
    asm volatile("cp.async.cg.shared.global [%0], [%1], 16;" :: "r"(s), "l"(g));
}
__device__ __forceinline__ void cp_commit() {
    asm volatile("cp.async.commit_group;");
}
__device__ __forceinline__ unsigned smaddr(const void* p) {
    unsigned a;
    asm("{.reg .u64 t; cvta.to.shared.u64 t, %1; cvt.u32.u64 %0, t;}" : "=r"(a) : "l"(p));
    return a;
}

// fp32 pair -> packed bf16 hi/lo (hi = rn(x), lo = rn(x - hi))
__device__ __forceinline__ void cvt_hilo(float2 v, unsigned& hi, unsigned& lo) {
    __nv_bfloat16 h0 = __float2bfloat16_rn(v.x);
    __nv_bfloat16 h1 = __float2bfloat16_rn(v.y);
    __nv_bfloat16 l0 = __float2bfloat16_rn(v.x - __bfloat162float(h0));
    __nv_bfloat16 l1 = __float2bfloat16_rn(v.y - __bfloat162float(h1));
    hi = (unsigned)__bfloat16_as_ushort(h0) | ((unsigned)__bfloat16_as_ushort(h1) << 16);
    lo = (unsigned)__bfloat16_as_ushort(l0) | ((unsigned)__bfloat16_as_ushort(l1) << 16);
}

// classic tensor-core mma (sm_80+ PTX, legal on compute_103)
__device__ __forceinline__ void mma16816(float* d, const unsigned* a, const unsigned* b) {
    asm volatile(
        "mma.sync.aligned.m16n8k16.row.col.f32.bf16.bf16.f32 "
        "{%0,%1,%2,%3}, {%4,%5,%6,%7}, {%8,%9}, {%0,%1,%2,%3};"
        : "+f"(d[0]), "+f"(d[1]), "+f"(d[2]), "+f"(d[3])
        : "r"(a[0]), "r"(a[1]), "r"(a[2]), "r"(a[3]), "r"(b[0]), "r"(b[1]));
}

// ---------------- K0: zero d_out, g_cnew, g_ohead, g_qabs ----------------
__global__ void k_init(float* __restrict__ out) {
    int i = blockIdx.x * 256 + threadIdx.x;       // 131072 threads
    g_qabs[i] = 0.f;
    if (i < BB * DD) { out[i] = 0.f; g_ohead[i] = 0.f; }
    if (i < BB * KVV) g_cnew[i] = 0.f;
}

// ---------------- K1: c_new = x @ w_compress (k-split, atomic) ----------------
__global__ __launch_bounds__(256) void k_compress(const float* __restrict__ x,
                                                  const float* __restrict__ wc) {
    __shared__ float xs[128][9];
    int kc = blockIdx.x;
    int tid = threadIdx.x;
    for (int i = tid; i < 1024; i += 256) {
        int k = i >> 3, b = i & 7;
        xs[k][b] = x[b * DD + kc * 128 + k];
    }
    __syncthreads();
    float2 acc[BB];
    #pragma unroll
    for (int b = 0; b < BB; b++) acc[b] = make_float2(0.f, 0.f);
    const float* wp = wc + (size_t)kc * 128 * KVV + tid * 2;
    #pragma unroll 8
    for (int k = 0; k < 128; k++) {
        float2 w2 = *(const float2*)(wp + (size_t)k * KVV);
        float4 x0 = *(const float4*)&xs[k][0];
        float4 x1 = *(const float4*)&xs[k][4];
        acc[0] = ffma2s(x0.x, w2, acc[0]);
        acc[1] = ffma2s(x0.y, w2, acc[1]);
        acc[2] = ffma2s(x0.z, w2, acc[2]);
        acc[3] = ffma2s(x0.w, w2, acc[3]);
        acc[4] = ffma2s(x1.x, w2, acc[4]);
        acc[5] = ffma2s(x1.y, w2, acc[5]);
        acc[6] = ffma2s(x1.z, w2, acc[6]);
        acc[7] = ffma2s(x1.w, w2, acc[7]);
    }
    #pragma unroll
    for (int b = 0; b < BB; b++) {
        atomicAdd(&g_cnew[b * KVV + tid * 2 + 0], acc[b].x);
        atomicAdd(&g_cnew[b * KVV + tid * 2 + 1], acc[b].y);
    }
}

// ---------------- K2: q_abs (scale folded into x), atomic accumulate ----------------
__global__ __launch_bounds__(128) void k_qabs(const float* __restrict__ x,
                                              const float* __restrict__ aqk) {
    __shared__ float xs[256][9];
    int kc = blockIdx.x;
    int h  = blockIdx.y;
    int tid = threadIdx.x;
    for (int i = tid; i < 2048; i += 128) {
        int k = i >> 3, b = i & 7;
        xs[k][b] = x[b * DD + kc * 256 + k] * SCALEF;
    }
    __syncthreads();
    float2 acc[BB][2];
    #pragma unroll
    for (int b = 0; b < BB; b++) {
        acc[b][0] = make_float2(0.f, 0.f);
        acc[b][1] = make_float2(0.f, 0.f);
    }
    const float* ap = aqk + ((size_t)h * DD + (size_t)kc * 256) * KVV + tid * 4;
    #pragma unroll 8
    for (int k = 0; k < 256; k++) {
        float4 a4 = *(const float4*)(ap + (size_t)k * KVV);
        float2 alo = make_float2(a4.x, a4.y);
        float2 ahi = make_float2(a4.z, a4.w);
        float4 x0 = *(const float4*)&xs[k][0];
        float4 x1 = *(const float4*)&xs[k][4];
        acc[0][0] = ffma2s(x0.x, alo, acc[0][0]); acc[0][1] = ffma2s(x0.x, ahi, acc[0][1]);
        acc[1][0] = ffma2s(x0.y, alo, acc[1][0]); acc[1][1] = ffma2s(x0.y, ahi, acc[1][1]);
        acc[2][0] = ffma2s(x0.z, alo, acc[2][0]); acc[2][1] = ffma2s(x0.z, ahi, acc[2][1]);
        acc[3][0] = ffma2s(x0.w, alo, acc[3][0]); acc[3][1] = ffma2s(x0.w, ahi, acc[3][1]);
        acc[4][0] = ffma2s(x1.x, alo, acc[4][0]); acc[4][1] = ffma2s(x1.x, ahi, acc[4][1]);
        acc[5][0] = ffma2s(x1.y, alo, acc[5][0]); acc[5][1] = ffma2s(x1.y, ahi, acc[5][1]);
        acc[6][0] = ffma2s(x1.z, alo, acc[6][0]); acc[6][1] = ffma2s(x1.z, ahi, acc[6][1]);
        acc[7][0] = ffma2s(x1.w, alo, acc[7][0]); acc[7][1] = ffma2s(x1.w, ahi, acc[7][1]);
    }
    #pragma unroll
    for (int b = 0; b < BB; b++) {
        float* dst = &g_qabs[((size_t)b * HH + h) * KVV + tid * 4];
        atomicAdd(dst + 0, acc[b][0].x);
        atomicAdd(dst + 1, acc[b][0].y);
        atomicAdd(dst + 2, acc[b][1].x);
        atomicAdd(dst + 3, acc[b][1].y);
    }
}

// ---------------- K3: scores via mma.sync, q pre-converted to bf16 hi/lo ----------------
// grid (sc=16, b=8); 512 threads = 16 warps; warp owns 32s x 32h tile.
// smem (floats): stage[2][512][36] @0/@18432; q_hi/q_lo u32[32][260] @36864/@45184.
#define SG_STG0 0
#define SG_STG1 18432
#define SG_QH 36864
#define SG_QL 45184
#define QW 260
#define SMEM_SC (53504 * 4)   // 214016 B

__device__ __forceinline__ void sc_issue(unsigned sb, const float* __restrict__ past_c,
                                         int b, int S0, int ck, int stg, int tid) {
    #pragma unroll
    for (int t = 0; t < 8; t++) {
        int i = tid + t * 512;
        int s = i >> 3, seg = i & 7;
        const float* row = (S0 + s < PASTN) ? past_c + ((size_t)b * PASTN + S0 + s) * KVV
                                            : g_cnew + b * KVV;
        cp_async16(sb + (unsigned)(stg + s * 36 + seg * 4) * 4u, row + ck * 32 + seg * 4);
    }
    cp_commit();
}

__global__ __launch_bounds__(512) void k_scores(const float* __restrict__ past_c) {
    extern __shared__ float sm[];
    unsigned sb = smaddr(sm);
    int sc = blockIdx.x, b = blockIdx.y;
    int tid = threadIdx.x;
    int w = tid >> 5, lane = tid & 31;
    int gid = lane >> 2, tig = lane & 3;
    int S0 = sc * 512;
    int SB = w * 32;
    unsigned* qh = (unsigned*)(sm + SG_QH);
    unsigned* ql = (unsigned*)(sm + SG_QL);

    // precompute q bf16 hi/lo once (8192 float2 over 512 threads)
    #pragma unroll
    for (int t = 0; t < 16; t++) {
        int i = tid + t * 512;
        int h = i >> 8, jp = i & 255;
        float2 v = *(const float2*)&g_qabs[((size_t)b * HH + h) * KVV + jp * 2];
        unsigned hw, lw;
        cvt_hilo(v, hw, lw);
        qh[h * QW + jp] = hw;
        ql[h * QW + jp] = lw;
    }
    // prologue: chunk 0
    sc_issue(sb, past_c, b, S0, 0, SG_STG0, tid);

    float d[2][4][4];
    #pragma unroll
    for (int m = 0; m < 2; m++)
        #pragma unroll
        for (int n = 0; n < 4; n++)
            #pragma unroll
            for (int c = 0; c < 4; c++) d[m][n][c] = 0.f;

    for (int ck = 0; ck < 16; ck++) {
        asm volatile("cp.async.wait_group 0;");
        __syncthreads();                       // chunk ck + q visible; prev compute done
        if (ck < 15)
            sc_issue(sb, past_c, b, S0, ck + 1, ((ck + 1) & 1) ? SG_STG1 : SG_STG0, tid);
        const float* A = sm + ((ck & 1) ? SG_STG1 : SG_STG0);
        #pragma unroll
        for (int ks = 0; ks < 2; ks++) {
            int k0 = ks * 16;
            unsigned ahi[2][4], alo[2][4], bhi[4][2], blo[4][2];
            #pragma unroll
            for (int m = 0; m < 2; m++) {
                const float* Ar = A + (SB + m * 16 + gid) * 36 + k0 + tig * 2;
                cvt_hilo(*(const float2*)(Ar),              ahi[m][0], alo[m][0]);
                cvt_hilo(*(const float2*)(Ar + 8 * 36),     ahi[m][1], alo[m][1]);
                cvt_hilo(*(const float2*)(Ar + 8),          ahi[m][2], alo[m][2]);
                cvt_hilo(*(const float2*)(Ar + 8 * 36 + 8), ahi[m][3], alo[m][3]);
            }
            int kw = ck * 16 + ks * 8 + tig;
            #pragma unroll
            for (int n = 0; n < 4; n++) {
                int hb = (n * 8 + gid) * QW + kw;
                bhi[n][0] = qh[hb];     blo[n][0] = ql[hb];
                bhi[n][1] = qh[hb + 4]; blo[n][1] = ql[hb + 4];
            }
            #pragma unroll
            for (int m = 0; m < 2; m++)
                #pragma unroll
                for (int n = 0; n < 4; n++) {
                    mma16816(d[m][n], ahi[m], bhi[n]);
                    mma16816(d[m][n], ahi[m], blo[n]);
                    mma16816(d[m][n], alo[m], bhi[n]);
                }
        }
    }

    // epilogue: stage D through smem (warp-private region in stage0), coalesced store
    __syncthreads();
    float* outw = sm + SG_STG0 + w * (32 * 33);
    #pragma unroll
    for (int m = 0; m < 2; m++)
        #pragma unroll
        for (int n = 0; n < 4; n++)
            #pragma unroll
            for (int c = 0; c < 4; c++) {
                int srow = m * 16 + gid + ((c >> 1) << 3);
                int hcol = n * 8 + tig * 2 + (c & 1);
                outw[hcol * 33 + srow] = d[m][n][c];
            }
    __syncwarp();
    #pragma unroll
    for (int h = 0; h < 32; h++)
        g_scores[((size_t)b * HH + h) * TOTALN + S0 + SB + lane] = outw[h * 33 + lane];
}

// ---------------- K4: row stats (m, 1/l) per (b,h) ----------------
__global__ __launch_bounds__(256) void k_mrow() {
    int bh = blockIdx.x;
    int tid = threadIdx.x;
    int w = tid >> 5, lane = tid & 31;
    const float* row = g_scores + (size_t)bh * TOTALN;
    float4 v[8];
    #pragma unroll
    for (int i = 0; i < 8; i++) v[i] = ((const float4*)row)[tid * 8 + i];
    float m = -1e30f;
    #pragma unroll
    for (int i = 0; i < 8; i++)
        m = fmaxf(m, fmaxf(fmaxf(v[i].x, v[i].y), fmaxf(v[i].z, v[i].w)));
    #pragma unroll
    for (int o = 16; o; o >>= 1) m = fmaxf(m, __shfl_xor_sync(0xffffffffu, m, o));
    __shared__ float redm[8], reds[8];
    if (lane == 0) redm[w] = m;
    __syncthreads();
    m = redm[0];
    #pragma unroll
    for (int i = 1; i < 8; i++) m = fmaxf(m, redm[i]);
    float s = 0.f;
    #pragma unroll
    for (int i = 0; i < 8; i++)
        s += __expf(v[i].x - m) + __expf(v[i].y - m) + __expf(v[i].z - m) + __expf(v[i].w - m);
    #pragma unroll
    for (int o = 16; o; o >>= 1) s += __shfl_xor_sync(0xffffffffu, s, o);
    if (lane == 0) reds[w] = s;
    __syncthreads();
    if (tid == 0) {
        s = reds[0] + reds[1] + reds[2] + reds[3] + reds[4] + reds[5] + reds[6] + reds[7];
        g_ml2[bh * 2 + 0] = m;
        g_ml2[bh * 2 + 1] = 1.f / s;
    }
}

// ---------------- K5: o_c partials via mma.sync (A = exp-weights bf16, B = c) ----------------
// grid (sc=16, b=8); 512 threads = 16 warps; warp owns 32h x 32n; accumulate over 16 chunks.
// smem (floats): cb[2][32s][524] @0/@16768; e_hi/e_lo u32[32h][20w] @33536/@34176.
#define OV_STG0 0
#define OV_STG1 16768
#define OV_EH 33536
#define OV_EL 34176
#define EW 20
#define SMEM_OV (34816 * 4)   // 139264 B

__global__ __launch_bounds__(512) void k_ov(const float* __restrict__ past_c) {
    extern __shared__ float sm[];
    __shared__ float msh[HH], ilsh[HH];
    unsigned sb = smaddr(sm);
    int sc = blockIdx.x, b = blockIdx.y;
    int tid = threadIdx.x;
    int w = tid >> 5, lane = tid & 31;
    int gid = lane >> 2, tig = lane & 3;
    int S0 = sc * 512;
    int n0 = w * 32;
    unsigned* eh = (unsigned*)(sm + OV_EH);
    unsigned* el = (unsigned*)(sm + OV_EL);
    if (tid < HH) {
        msh[tid]  = g_ml2[(b * HH + tid) * 2 + 0];
        ilsh[tid] = g_ml2[(b * HH + tid) * 2 + 1];
    }

    // prologue: chunk 0 (32 s x 512 n, row stride 524)
    #pragma unroll
    for (int t = 0; t < 8; t++) {
        int i = tid + t * 512;
        int s = i >> 7, n4 = i & 127;
        const float* row = (S0 + s < PASTN) ? past_c + ((size_t)b * PASTN + S0 + s) * KVV
                                            : g_cnew + b * KVV;
        cp_async16(sb + (unsigned)(OV_STG0 + s * 524 + n4 * 4) * 4u, row + n4 * 4);
    }
    cp_commit();

    float d[2][4][4];
    #pragma unroll
    for (int m = 0; m < 2; m++)
        #pragma unroll
        for (int n = 0; n < 4; n++)
            #pragma unroll
            for (int c = 0; c < 4; c++) d[m][n][c] = 0.f;

    for (int ch = 0; ch < 16; ch++) {
        int s0 = S0 + ch * 32;
        asm volatile("cp.async.wait_group 0;");
        __syncthreads();                   // chunk ch visible; prev compute done
        // e tile: [32h][32s] -> bf16 hi/lo (512 threads, 1 float2 each)
        {
            int h = tid >> 4, sp = tid & 15;
            float2 v = *(const float2*)&g_scores[((size_t)b * HH + h) * TOTALN + s0 + sp * 2];
            float il = ilsh[h], mm = msh[h];
            float2 e2 = make_float2(__expf(v.x - mm) * il, __expf(v.y - mm) * il);
            unsigned hw, lw;
            cvt_hilo(e2, hw, lw);
            eh[h * EW + sp] = hw;
            el[h * EW + sp] = lw;
        }
        if (ch < 15) {                     // issue next into other buffer
            int s0n = s0 + 32;
            int stg = ((ch + 1) & 1) ? OV_STG1 : OV_STG0;
            #pragma unroll
            for (int t = 0; t < 8; t++) {
                int i = tid + t * 512;
                int s = i >> 7, n4 = i & 127;
                const float* row = (s0n + s < PASTN) ? past_c + ((size_t)b * PASTN + s0n + s) * KVV
                                                     : g_cnew + b * KVV;
                cp_async16(sb + (unsigned)(stg + s * 524 + n4 * 4) * 4u, row + n4 * 4);
            }
            cp_commit();
        }
        __syncthreads();                   // e visible
        const float* cbuf = sm + ((ch & 1) ? OV_STG1 : OV_STG0);
        #pragma unroll
        for (int ks = 0; ks < 2; ks++) {
            int k0 = ks * 16;
            unsigned ahi[2][4], alo[2][4], bhi[4][2], blo[4][2];
            #pragma unroll
            for (int m = 0; m < 2; m++) {
                int base = (m * 16 + gid) * EW + ks * 8 + tig;
                ahi[m][0] = eh[base];        alo[m][0] = el[base];
                ahi[m][1] = eh[base + 160];  alo[m][1] = el[base + 160];   // +8 rows
                ahi[m][2] = eh[base + 4];    alo[m][2] = el[base + 4];     // +8 cols
                ahi[m][3] = eh[base + 164];  alo[m][3] = el[base + 164];
            }
            #pragma unroll
            for (int n = 0; n < 4; n++) {
                int nn = n0 + n * 8 + gid;
                int kr = k0 + tig * 2;
                float v0 = cbuf[kr * 524 + nn];
                float v1 = cbuf[(kr + 1) * 524 + nn];
                cvt_hilo(make_float2(v0, v1), bhi[n][0], blo[n][0]);
                float v2 = cbuf[(kr + 8) * 524 + nn];
                float v3 = cbuf[(kr + 9) * 524 + nn];
                cvt_hilo(make_float2(v2, v3), bhi[n][1], blo[n][1]);
            }
            #pragma unroll
            for (int m = 0; m < 2; m++)
                #pragma unroll
                for (int n = 0; n < 4; n++) {
                    mma16816(d[m][n], ahi[m], bhi[n]);
                    mma16816(d[m][n], ahi[m], blo[n]);
                    mma16816(d[m][n], alo[m], bhi[n]);
                }
        }
    }
    // store: warp owns full (h, n0..n0+31) tile — direct float2 stores
    size_t obase = ((size_t)sc * BB + b) * HH * KVV;
    #pragma unroll
    for (int m = 0; m < 2; m++)
        #pragma unroll
        for (int n = 0; n < 4; n++) {
            int row = m * 16 + gid;
            int col = n0 + n * 8 + tig * 2;
            *(float2*)&g_opart[obase + (size_t)row * KVV + col] =
                make_float2(d[m][n][0], d[m][n][1]);
            *(float2*)&g_opart[obase + (size_t)(row + 8) * KVV + col] =
                make_float2(d[m][n][2], d[m][n][3]);
        }
}

// reduce NSC s-partials -> g_oc
__global__ void k_redo() {
    int i = blockIdx.x * 256 + threadIdx.x;
    const float4* p = (const float4*)g_opart;
    float4 s = make_float4(0.f, 0.f, 0.f, 0.f);
    #pragma unroll
    for (int c = 0; c < NSC; c++) {
        float4 t = p[c * 32768 + i];
        s.x += t.x; s.y += t.y; s.z += t.z; s.w += t.w;
    }
    ((float4*)g_oc)[i] = s;
}

// ---------------- K6: per-head v-up (n-split, atomic) ----------------
__global__ __launch_bounds__(128) void k_vup(const float* __restrict__ wv) {
    __shared__ float od[128][9];
    int h = blockIdx.x, nc = blockIdx.y;
    int tid = threadIdx.x;
    int jp = tid & 63, g = tid >> 6;
    for (int i = tid; i < 1024; i += 128) {
        int n = i >> 3, b = i & 7;
        od[n][b] = g_oc[((size_t)b * HH + h) * KVV + nc * 128 + n];
    }
    __syncthreads();
    float2 acc[BB];
    #pragma unroll
    for (int b = 0; b < BB; b++) acc[b] = make_float2(0.f, 0.f);
    const float* wp = wv + (size_t)(nc * 128 + g * 64) * (HH * HDD) + h * HDD + jp * 2;
    #pragma unroll 8
    for (int n = 0; n < 64; n++) {
        float2 w2 = *(const float2*)(wp + (size_t)n * (HH * HDD));
        float4 o0 = *(const float4*)&od[g * 64 + n][0];
        float4 o1 = *(const float4*)&od[g * 64 + n][4];
        acc[0] = ffma2s(o0.x, w2, acc[0]);
        acc[1] = ffma2s(o0.y, w2, acc[1]);
        acc[2] = ffma2s(o0.z, w2, acc[2]);
        acc[3] = ffma2s(o0.w, w2, acc[3]);
        acc[4] = ffma2s(o1.x, w2, acc[4]);
        acc[5] = ffma2s(o1.y, w2, acc[5]);
        acc[6] = ffma2s(o1.z, w2, acc[6]);
        acc[7] = ffma2s(o1.w, w2, acc[7]);
    }
    #pragma unroll
    for (int b = 0; b < BB; b++) {
        atomicAdd(&g_ohead[b * DD + h * HDD + jp * 2 + 0], acc[b].x);
        atomicAdd(&g_ohead[b * DD + h * HDD + jp * 2 + 1], acc[b].y);
    }
}

// ---------------- K7: out = out_head @ w_o (m-split over 16, atomic) ----------------
__global__ __launch_bounds__(128) void k_oproj(const float* __restrict__ wo,
                                               float* __restrict__ out) {
    __shared__ float ohd[256][9];
    int dt = blockIdx.x, mc = blockIdx.y;
    int tid = threadIdx.x;
    for (int i = tid; i < 2048; i += 128) {
        int m = i >> 3, b = i & 7;
        ohd[m][b] = g_ohead[b * DD + mc * 256 + m];
    }
    __syncthreads();
    float2 acc[BB];
    #pragma unroll
    for (int b = 0; b < BB; b++) acc[b] = make_float2(0.f, 0.f);
    const float* wp = wo + (size_t)mc * 256 * DD + dt * 256 + tid * 2;
    #pragma unroll 8
    for (int m = 0; m < 256; m++) {
        float2 w2 = *(const float2*)(wp + (size_t)m * DD);
        float4 o0 = *(const float4*)&ohd[m][0];
        float4 o1 = *(const float4*)&ohd[m][4];
        acc[0] = ffma2s(o0.x, w2, acc[0]);
        acc[1] = ffma2s(o0.y, w2, acc[1]);
        acc[2] = ffma2s(o0.z, w2, acc[2]);
        acc[3] = ffma2s(o0.w, w2, acc[3]);
        acc[4] = ffma2s(o1.x, w2, acc[4]);
        acc[5] = ffma2s(o1.y, w2, acc[5]);
        acc[6] = ffma2s(o1.z, w2, acc[6]);
        acc[7] = ffma2s(o1.w, w2, acc[7]);
    }
    #pragma unroll
    for (int b = 0; b < BB; b++) {
        atomicAdd(&out[b * DD + dt * 256 + tid * 2 + 0], acc[b].x);
        atomicAdd(&out[b * DD + dt * 256 + tid * 2 + 1], acc[b].y);
    }
}

// ---------------- launch ----------------
extern "C" void kernel_launch(void* const* d_in, const int* in_sizes, int n_in,
                              void* d_out, int out_size) {
    const float* x      = (const float*)d_in[0];
    const float* past_c = (const float*)d_in[1];
    const float* aqk    = (const float*)d_in[2];
    const float* wc     = (const float*)d_in[3];
    const float* wv     = (const float*)d_in[4];
    const float* wo     = (const float*)d_in[5];
    float* out = (float*)d_out;

    cudaFuncSetAttribute(k_scores, cudaFuncAttributeMaxDynamicSharedMemorySize, SMEM_SC);
    cudaFuncSetAttribute(k_ov,     cudaFuncAttributeMaxDynamicSharedMemorySize, SMEM_OV);

    k_init<<<512, 256>>>(out);                          // idx 0
    k_compress<<<32, 256>>>(x, wc);                     // idx 1
    k_qabs<<<dim3(NKC, 32), 128>>>(x, aqk);             // idx 2
    k_scores<<<dim3(16, 8), 512, SMEM_SC>>>(past_c);    // idx 3  <- profiled
    k_mrow<<<256, 256>>>();                             // idx 4
    k_ov<<<dim3(NSC, 8), 512, SMEM_OV>>>(past_c);       // idx 5
    k_redo<<<128, 256>>>();                             // idx 6
    k_vup<<<dim3(32, 4), 128>>>(wv);                    // idx 7
    k_oproj<<<dim3(16, 16), 128>>>(wo, out);            // idx 8
}